// round 8
// baseline (speedup 1.0000x reference)
#include <cuda_runtime.h>
#include <cuda_bf16.h>
#include <cstdint>

// ---------------- problem constants ----------------
#define BB    2
#define QN    1024
#define PAST  1024
#define MAXC  4096
#define HH    32
#define HKV   8
#define DD    128
#define HID   4096
#define KLEN  (PAST + QN)          // 2048
#define NQKV  ((HH + 2*HKV) * DD)  // 6144
#define GROUPS (HH / HKV)
#define SCALE 0.08838834764831845f

#define OUT_SZ1 (BB*QN*HID)
#define CACHE_SZ (BB*HKV*MAXC*DD)

// ---------------- scratch (device globals) ----------------
__device__ __align__(16) float g_qkv  [BB*QN*NQKV];
__device__ __align__(16) float g_attnO[BB*HH*QN*DD];

__device__ __align__(16) __nv_bfloat16 gA_hi [BB*QN*HID];
__device__ __align__(16) __nv_bfloat16 gA_lo [BB*QN*HID];
__device__ __align__(16) __nv_bfloat16 gWq_hi[NQKV*HID];
__device__ __align__(16) __nv_bfloat16 gWq_lo[NQKV*HID];
__device__ __align__(16) __nv_bfloat16 gWo_hi[HID*HKV*DD];
__device__ __align__(16) __nv_bfloat16 gWo_lo[HID*HKV*DD];
__device__ __align__(16) __nv_bfloat16 gXo_hi[BB*QN*HKV*DD];
__device__ __align__(16) __nv_bfloat16 gXo_lo[BB*QN*HKV*DD];

// attention bf16 hi/lo operands
__device__ __align__(16) __nv_bfloat16 gQ_hi [BB*HH*QN*DD];
__device__ __align__(16) __nv_bfloat16 gQ_lo [BB*HH*QN*DD];
__device__ __align__(16) __nv_bfloat16 gKc_hi[BB*HKV*KLEN*DD];
__device__ __align__(16) __nv_bfloat16 gKc_lo[BB*HKV*KLEN*DD];
__device__ __align__(16) __nv_bfloat16 gVc_hi[BB*HKV*KLEN*DD];
__device__ __align__(16) __nv_bfloat16 gVc_lo[BB*HKV*KLEN*DD];

// ================= PTX helpers (sm_80+ portable subset) =================
__device__ __forceinline__ uint32_t smem_u32(const void* p) {
    uint32_t a;
    asm("{ .reg .u64 t; cvta.to.shared.u64 t, %1; cvt.u32.u64 %0, t; }" : "=r"(a) : "l"(p));
    return a;
}
__device__ __forceinline__ void ldm_x4(uint32_t* r, uint32_t addr) {
    asm volatile("ldmatrix.sync.aligned.m8n8.x4.shared.b16 {%0,%1,%2,%3}, [%4];"
                 : "=r"(r[0]), "=r"(r[1]), "=r"(r[2]), "=r"(r[3]) : "r"(addr));
}
__device__ __forceinline__ void ldm_x4t(uint32_t* r, uint32_t addr) {
    asm volatile("ldmatrix.sync.aligned.m8n8.x4.trans.shared.b16 {%0,%1,%2,%3}, [%4];"
                 : "=r"(r[0]), "=r"(r[1]), "=r"(r[2]), "=r"(r[3]) : "r"(addr));
}
__device__ __forceinline__ void mma_bf16(float* d, const uint32_t* a, const uint32_t* b) {
    asm volatile(
        "mma.sync.aligned.m16n8k16.row.col.f32.bf16.bf16.f32 "
        "{%0,%1,%2,%3}, {%4,%5,%6,%7}, {%8,%9}, {%0,%1,%2,%3};"
        : "+f"(d[0]), "+f"(d[1]), "+f"(d[2]), "+f"(d[3])
        : "r"(a[0]), "r"(a[1]), "r"(a[2]), "r"(a[3]), "r"(b[0]), "r"(b[1]));
}
__device__ __forceinline__ void cp16(uint32_t dst, const void* src) {
    asm volatile("cp.async.cg.shared.global [%0], [%1], 16;" :: "r"(dst), "l"(src));
}
__device__ __forceinline__ uint32_t pack_bf2(float x, float y) {
    __nv_bfloat162 h;
    h.x = __float2bfloat16(x); h.y = __float2bfloat16(y);
    return *(uint32_t*)&h;
}

// ================= hi/lo conversion kernels =================
__global__ void conv_hilo(const float* __restrict__ src,
                          __nv_bfloat16* __restrict__ hi, __nv_bfloat16* __restrict__ lo, int n) {
    int i = blockIdx.x * 256 + threadIdx.x;
    if (i >= n) return;
    float x = src[i];
    __nv_bfloat16 h = __float2bfloat16(x);
    hi[i] = h;
    lo[i] = __float2bfloat16(x - __bfloat162float(h));
}

// src [K][N] fp32 -> hi/lo [N][K] bf16
__global__ void conv_hilo_T(const float* __restrict__ src,
                            __nv_bfloat16* __restrict__ hi, __nv_bfloat16* __restrict__ lo,
                            int K, int N) {
    __shared__ float t[32][33];
    int bn = blockIdx.x * 32, bk = blockIdx.y * 32;
    int x = threadIdx.x, y = threadIdx.y;
    #pragma unroll
    for (int i = 0; i < 32; i += 8)
        t[y + i][x] = src[(long)(bk + y + i) * N + bn + x];
    __syncthreads();
    #pragma unroll
    for (int i = 0; i < 32; i += 8) {
        float v = t[x][y + i];
        long o = (long)(bn + y + i) * K + bk + x;
        __nv_bfloat16 h = __float2bfloat16(v);
        hi[o] = h;
        lo[o] = __float2bfloat16(v - __bfloat162float(h));
    }
}

// PAST rows of the caches -> hi/lo (reads original input caches)
__global__ void kv_hilo_past(const float* __restrict__ kc, const float* __restrict__ vc) {
    long i = (long)blockIdx.x * 256 + threadIdx.x;
    if (i >= (long)BB * HKV * PAST * DD) return;
    int d = (int)(i & (DD - 1));
    long t = i >> 7;
    int pos = (int)(t & (PAST - 1));
    t >>= 10;                               // t = b*HKV + h
    long src = (t * MAXC + pos) * DD + d;
    long dst = (t * KLEN + pos) * DD + d;
    float kx = kc[src];
    __nv_bfloat16 kh = __float2bfloat16(kx);
    gKc_hi[dst] = kh;
    gKc_lo[dst] = __float2bfloat16(kx - __bfloat162float(kh));
    float vx = vc[src];
    __nv_bfloat16 vh = __float2bfloat16(vx);
    gVc_hi[dst] = vh;
    gVc_lo[dst] = __float2bfloat16(vx - __bfloat162float(vh));
}

// ================= warp-MMA hi/lo GEMM (3-stage, swizzled, 64x64 warp tile) =================
#define TILE_B  8192
#define STAGE_B (4 * TILE_B)              // Ahi,Alo,Bhi,Blo = 32768
#define NST     3
#define GEMM_SMEM (NST * STAGE_B)         // 98304

__device__ __forceinline__ uint32_t swz(int row, int ch) {
    return (uint32_t)(row * 64 + ((ch ^ ((row >> 1) & 3)) << 4));
}

__device__ __forceinline__ void fill_stage(
    uint32_t sb, int kt, int m0, int n0, int K,
    const __nv_bfloat16* Ahi, const __nv_bfloat16* Alo,
    const __nv_bfloat16* Bhi, const __nv_bfloat16* Blo, int tid)
{
    long k0 = (long)kt * 32;
    const __nv_bfloat16* bases[4] = {Ahi, Alo, Bhi, Blo};
    #pragma unroll
    for (int t = 0; t < 4; t++) {
        const __nv_bfloat16* bp = bases[t];
        int r0 = (t < 2) ? m0 : n0;
        #pragma unroll
        for (int i = 0; i < 4; i++) {
            int idx = tid + i * 128;
            int row = idx >> 2, ch = idx & 3;
            cp16(sb + t * TILE_B + swz(row, ch), bp + (long)(r0 + row) * K + k0 + ch * 8);
        }
    }
}

__global__ void __launch_bounds__(128, 2) gemm_mma(
    const __nv_bfloat16* __restrict__ Ahi, const __nv_bfloat16* __restrict__ Alo,
    const __nv_bfloat16* __restrict__ Bhi, const __nv_bfloat16* __restrict__ Blo,
    float* __restrict__ C, int M, int N, int K)
{
    extern __shared__ char smraw[];
    uint32_t s0 = smem_u32(smraw);
    int tid = threadIdx.x, lane = tid & 31, wid = tid >> 5;
    int wm = wid & 1, wn = wid >> 1;
    int m0 = blockIdx.y * 128, n0 = blockIdx.x * 128;

    float acc[4][8][4];
    #pragma unroll
    for (int i = 0; i < 4; i++)
        #pragma unroll
        for (int j = 0; j < 8; j++)
            #pragma unroll
            for (int k = 0; k < 4; k++) acc[i][j][k] = 0.f;

    int nk = K >> 5;
    fill_stage(s0, 0, m0, n0, K, Ahi, Alo, Bhi, Blo, tid);
    asm volatile("cp.async.commit_group;" ::: "memory");
    fill_stage(s0 + STAGE_B, 1, m0, n0, K, Ahi, Alo, Bhi, Blo, tid);
    asm volatile("cp.async.commit_group;" ::: "memory");

    int a_row = wm * 64 + (lane & 15);
    int a_cb  = lane >> 4;
    int b_row = wn * 64 + (lane & 7) + (lane >> 4) * 8;
    int b_cb  = (lane >> 3) & 1;

    for (int kt = 0; kt < nk; kt++) {
        asm volatile("cp.async.wait_group 1;" ::: "memory");
        __syncthreads();

        if (kt + 2 < nk)
            fill_stage(s0 + ((kt + 2) % NST) * STAGE_B, kt + 2, m0, n0, K, Ahi, Alo, Bhi, Blo, tid);
        asm volatile("cp.async.commit_group;" ::: "memory");

        uint32_t sb = s0 + (kt % NST) * STAGE_B;
        #pragma unroll
        for (int ks = 0; ks < 2; ks++) {
            uint32_t a[2][4][4];
            #pragma unroll
            for (int hl = 0; hl < 2; hl++)
                #pragma unroll
                for (int mt = 0; mt < 4; mt++)
                    ldm_x4(a[hl][mt], sb + hl * TILE_B + swz(a_row + mt * 16, ks * 2 + a_cb));
            #pragma unroll
            for (int np = 0; np < 4; np++) {
                uint32_t bh[4], bl[4];
                uint32_t bo = swz(b_row + np * 16, ks * 2 + b_cb);
                ldm_x4(bh, sb + 2 * TILE_B + bo);
                ldm_x4(bl, sb + 3 * TILE_B + bo);
                #pragma unroll
                for (int mt = 0; mt < 4; mt++)
                    #pragma unroll
                    for (int nt = 0; nt < 2; nt++) {
                        float* d = acc[mt][np * 2 + nt];
                        mma_bf16(d, a[0][mt], &bh[nt * 2]);
                        mma_bf16(d, a[0][mt], &bl[nt * 2]);
                        mma_bf16(d, a[1][mt], &bh[nt * 2]);
                    }
            }
        }
    }

    int row0 = m0 + wm * 64 + (lane >> 2);
    int col0 = n0 + wn * 64 + (lane & 3) * 2;
    #pragma unroll
    for (int mt = 0; mt < 4; mt++)
        #pragma unroll
        for (int nt = 0; nt < 8; nt++) {
            float* d = acc[mt][nt];
            long r = row0 + mt * 16;
            long c = col0 + nt * 8;
            *(float2*)(C + r * N + c)       = make_float2(d[0], d[1]);
            *(float2*)(C + (r + 8) * N + c) = make_float2(d[2], d[3]);
        }
}

// ---------------- RMSNorm + RoPE + scatter + fused hi/lo emission ----------------
__global__ void qkv_post_kernel(const float* __restrict__ rope,
                                const int*   __restrict__ start,
                                const float* __restrict__ qw,
                                const float* __restrict__ kw,
                                float* __restrict__ out_k,
                                float* __restrict__ out_v)
{
    int slot = blockIdx.x;
    int q    = blockIdx.y;
    int b    = blockIdx.z;
    int tid  = threadIdx.x;
    long row = ((long)b * QN + q) * NQKV;
    float x = g_qkv[row + (long)slot * DD + tid];
    int pos = start[b] + q;

    if (slot >= 40) {  // V: raw scatter + hi/lo
        int h = slot - 40;
        out_v[(((long)b * HKV + h) * MAXC + pos) * DD + tid] = x;
        long vi = (((long)b * HKV + h) * KLEN + pos) * DD + tid;
        __nv_bfloat16 vh = __float2bfloat16(x);
        gVc_hi[vi] = vh;
        gVc_lo[vi] = __float2bfloat16(x - __bfloat162float(vh));
        return;
    }

    __shared__ float red[4];
    __shared__ float sm[DD];
    float v2 = x * x;
    #pragma unroll
    for (int m = 16; m; m >>= 1) v2 += __shfl_xor_sync(0xffffffffu, v2, m);
    if ((tid & 31) == 0) red[tid >> 5] = v2;
    __syncthreads();
    float tot = red[0] + red[1] + red[2] + red[3];
    float scl = rsqrtf(tot * (1.f / DD) + 1e-6f);
    const float* w = (slot < 32) ? qw : kw;
    sm[tid] = x * scl * w[tid];
    __syncthreads();

    int i = (tid < 64) ? tid : tid - 64;
    float c = rope[(long)pos * DD + i];
    float s = rope[(long)pos * DD + 64 + i];
    float x1 = sm[i], x2 = sm[i + 64];
    float o = (tid < 64) ? (x1 * c - x2 * s) : (x2 * c + x1 * s);

    if (slot < 32) {   // Q: scaled hi/lo
        float xs = o * SCALE;
        long qi = (((long)b * HH + slot) * QN + q) * DD + tid;
        __nv_bfloat16 qh = __float2bfloat16(xs);
        gQ_hi[qi] = qh;
        gQ_lo[qi] = __float2bfloat16(xs - __bfloat162float(qh));
    } else {           // K: fp32 scatter + hi/lo
        int h = slot - 32;
        out_k[(((long)b * HKV + h) * MAXC + pos) * DD + tid] = o;
        long ki = (((long)b * HKV + h) * KLEN + pos) * DD + tid;
        __nv_bfloat16 kh = __float2bfloat16(o);
        gKc_hi[ki] = kh;
        gKc_lo[ki] = __float2bfloat16(o - __bfloat162float(kh));
    }
}

// ================= tensor-core flash attention (bf16 hi/lo, 2 heads/CTA) =================
#define APITCHB 272
#define AQ 64
#define ATILE (AQ * APITCHB)               // 17408 per hi or lo
#define ATTN_SMEM (8 * ATILE)              // Q(2 heads x hi/lo) + K(hi/lo) + V(hi/lo) = 139264

__device__ __forceinline__ void load_tile64_256(uint32_t dst,
    const __nv_bfloat16* hi, const __nv_bfloat16* lo, long rowbase, int tid)
{
    #pragma unroll
    for (int i = 0; i < 4; i++) {
        int idx = tid + i * 256;
        int row = idx >> 4, ch = idx & 15;
        uint32_t d = dst + row * APITCHB + ch * 16;
        const long off = rowbase + (long)row * DD + (ch << 3);
        cp16(d, hi + off);
        cp16(d + ATILE, lo + off);
    }
}

__global__ void __launch_bounds__(256, 1) attn_mma()
{
    extern __shared__ char smraw[];
    uint32_t sQb = smem_u32(smraw);
    uint32_t sK  = sQb + 4 * ATILE;
    uint32_t sV  = sK  + 2 * ATILE;
    int tid = threadIdx.x, lane = tid & 31, wid = tid >> 5;
    int wg = wid >> 2;              // head sub-index (0/1)
    int w  = wid & 3;               // 16-row group within head
    int qt = blockIdx.x, hy = blockIdx.y, b = blockIdx.z;
    int h = hy * 2 + wg;
    int kvh = hy >> 1;
    int q0 = qt * 64;
    uint32_t sQ = sQb + wg * 2 * ATILE;

    long kvbase = (long)(b * HKV + kvh) * KLEN * DD;

    // prologue: both heads' Q + K chunk 0 in one commit group
    #pragma unroll
    for (int hh = 0; hh < 2; hh++)
        load_tile64_256(sQb + hh * 2 * ATILE, gQ_hi, gQ_lo,
                        ((long)(b * HH + hy * 2 + hh) * QN + q0) * DD, tid);
    load_tile64_256(sK, gKc_hi, gKc_lo, kvbase, tid);
    asm volatile("cp.async.commit_group;" ::: "memory");

    const int nc = 17 + qt;

    float O[16][4];
    #pragma unroll
    for (int i = 0; i < 16; i++)
        #pragma unroll
        for (int j = 0; j < 4; j++) O[i][j] = 0.f;
    float m0 = -1e30f, m1 = -1e30f, l0 = 0.f, l1 = 0.f;

    const int a_row  = w * 16 + (lane & 15);
    const int a_kb   = (lane >> 4) * 16;
    const int b_row  = (lane & 7) + (lane >> 4) * 8;
    const int b_kb   = ((lane >> 3) & 1) * 16;
    const int v_row  = lane & 15;
    const int v_col  = (lane >> 4) * 8;

    for (int c = 0; c < nc; c++) {
        int kb = c * 64;
        asm volatile("cp.async.wait_group 0;" ::: "memory");
        __syncthreads();

        load_tile64_256(sV, gVc_hi, gVc_lo, kvbase + (long)kb * DD, tid);
        asm volatile("cp.async.commit_group;" ::: "memory");

        // ---- S = Q K^T ----
        float S[8][4];
        #pragma unroll
        for (int j = 0; j < 8; j++)
            #pragma unroll
            for (int k = 0; k < 4; k++) S[j][k] = 0.f;

        #pragma unroll
        for (int ks = 0; ks < 8; ks++) {
            uint32_t ah[4], al[4];
            uint32_t qa = sQ + a_row * APITCHB + ks * 32 + a_kb;
            ldm_x4(ah, qa);
            ldm_x4(al, qa + ATILE);
            #pragma unroll
            for (int np = 0; np < 4; np++) {
                uint32_t bh[4], bl[4];
                uint32_t ka = sK + (np * 16 + b_row) * APITCHB + ks * 32 + b_kb;
                ldm_x4(bh, ka);
                ldm_x4(bl, ka + ATILE);
                #pragma unroll
                for (int nt = 0; nt < 2; nt++) {
                    float* d = S[np * 2 + nt];
                    mma_bf16(d, ah, &bh[nt * 2]);
                    mma_bf16(d, ah, &bl[nt * 2]);
                    mma_bf16(d, al, &bh[nt * 2]);
                }
            }
        }

        if (c == nc - 1) {
            int klim0 = PAST + q0 + w * 16 + (lane >> 2);
            int klim1 = klim0 + 8;
            #pragma unroll
            for (int j = 0; j < 8; j++) {
                int col = kb + j * 8 + (lane & 3) * 2;
                if (col > klim0)     S[j][0] = -1e30f;
                if (col + 1 > klim0) S[j][1] = -1e30f;
                if (col > klim1)     S[j][2] = -1e30f;
                if (col + 1 > klim1) S[j][3] = -1e30f;
            }
        }

        // ---- online softmax ----
        float mx0 = -1e30f, mx1 = -1e30f;
        #pragma unroll
        for (int j = 0; j < 8; j++) {
            mx0 = fmaxf(mx0, fmaxf(S[j][0], S[j][1]));
            mx1 = fmaxf(mx1, fmaxf(S[j][2], S[j][3]));
        }
        mx0 = fmaxf(mx0, __shfl_xor_sync(0xffffffffu, mx0, 1));
        mx0 = fmaxf(mx0, __shfl_xor_sync(0xffffffffu, mx0, 2));
        mx1 = fmaxf(mx1, __shfl_xor_sync(0xffffffffu, mx1, 1));
        mx1 = fmaxf(mx1, __shfl_xor_sync(0xffffffffu, mx1, 2));
        float mn0 = fmaxf(m0, mx0), mn1 = fmaxf(m1, mx1);
        float al0 = __expf(m0 - mn0), al1 = __expf(m1 - mn1);
        float r0 = 0.f, r1 = 0.f;
        #pragma unroll
        for (int j = 0; j < 8; j++) {
            S[j][0] = __expf(S[j][0] - mn0);
            S[j][1] = __expf(S[j][1] - mn0);
            S[j][2] = __expf(S[j][2] - mn1);
            S[j][3] = __expf(S[j][3] - mn1);
            r0 += S[j][0] + S[j][1];
            r1 += S[j][2] + S[j][3];
        }
        r0 += __shfl_xor_sync(0xffffffffu, r0, 1);
        r0 += __shfl_xor_sync(0xffffffffu, r0, 2);
        r1 += __shfl_xor_sync(0xffffffffu, r1, 1);
        r1 += __shfl_xor_sync(0xffffffffu, r1, 2);
        l0 = l0 * al0 + r0;
        l1 = l1 * al1 + r1;
        m0 = mn0; m1 = mn1;
        #pragma unroll
        for (int i = 0; i < 16; i++) {
            O[i][0] *= al0; O[i][1] *= al0;
            O[i][2] *= al1; O[i][3] *= al1;
        }

        // ---- P -> bf16 hi/lo A-frags ----
        uint32_t pa_h[4][4], pa_l[4][4];
        #pragma unroll
        for (int kt = 0; kt < 4; kt++) {
            int j0 = 2 * kt, j1 = 2 * kt + 1;
            float v00 = S[j0][0], v01 = S[j0][1], v02 = S[j0][2], v03 = S[j0][3];
            float v10 = S[j1][0], v11 = S[j1][1], v12 = S[j1][2], v13 = S[j1][3];
            pa_h[kt][0] = pack_bf2(v00, v01);
            pa_h[kt][1] = pack_bf2(v02, v03);
            pa_h[kt][2] = pack_bf2(v10, v11);
            pa_h[kt][3] = pack_bf2(v12, v13);
            __nv_bfloat162* hp;
            hp = (__nv_bfloat162*)&pa_h[kt][0];
            pa_l[kt][0] = pack_bf2(v00 - __bfloat162float(hp->x), v01 - __bfloat162float(hp->y));
            hp = (__nv_bfloat162*)&pa_h[kt][1];
            pa_l[kt][1] = pack_bf2(v02 - __bfloat162float(hp->x), v03 - __bfloat162float(hp->y));
            hp = (__nv_bfloat162*)&pa_h[kt][2];
            pa_l[kt][2] = pack_bf2(v10 - __bfloat162float(hp->x), v11 - __bfloat162float(hp->y));
            hp = (__nv_bfloat162*)&pa_h[kt][3];
            pa_l[kt][3] = pack_bf2(v12 - __bfloat162float(hp->x), v13 - __bfloat162float(hp->y));
        }

        __syncthreads();
        if (c + 1 < nc) {
            load_tile64_256(sK, gKc_hi, gKc_lo, kvbase + (long)(kb + 64) * DD, tid);
            asm volatile("cp.async.commit_group;" ::: "memory");
            asm volatile("cp.async.wait_group 1;" ::: "memory");
        } else {
            asm volatile("cp.async.wait_group 0;" ::: "memory");
        }
        __syncthreads();

        // ---- O += P V ----
        #pragma unroll
        for (int kt = 0; kt < 4; kt++) {
            #pragma unroll
            for (int np = 0; np < 8; np++) {
                uint32_t vh[4], vl[4];
                uint32_t va = sV + (kt * 16 + v_row) * APITCHB + (np * 16 + v_col) * 2;
                ldm_x4t(vh, va);
                ldm_x4t(vl, va + ATILE);
                #pragma unroll
                for (int nt = 0; nt < 2; nt++) {
                    float* d = O[np * 2 + nt];
                    mma_bf16(d, pa_h[kt], &vh[nt * 2]);
                    mma_bf16(d, pa_h[kt], &vl[nt * 2]);
                    mma_bf16(d, pa_l[kt], &vh[nt * 2]);
                }
            }
        }
        __syncthreads();
    }

    float inv0 = 1.f / l0, inv1 = 1.f / l1;
    int row0 = q0 + w * 16 + (lane >> 2);
    float* ob = g_attnO + ((long)(b * HH + h) * QN) * DD;
    #pragma unroll
    for (int np = 0; np < 16; np++) {
        int col = np * 8 + (lane & 3) * 2;
        *(float2*)(ob + (long)row0 * DD + col)       = make_float2(O[np][0] * inv0, O[np][1] * inv0);
        *(float2*)(ob + (long)(row0 + 8) * DD + col) = make_float2(O[np][2] * inv1, O[np][3] * inv1);
    }
}

// ---------------- group sum + hi/lo conversion ----------------
__global__ void group_sum_kernel()
{
    long i = (long)blockIdx.x * 256 + threadIdx.x;
    if (i >= (long)BB * QN * HKV * DD) return;
    int d = (int)(i & (DD - 1));
    long t = i >> 7;
    int kvh = (int)(t & (HKV - 1));
    t >>= 3;
    int q = (int)(t % QN);
    int b = (int)(t / QN);
    float sum = 0.f;
    #pragma unroll
    for (int g = 0; g < GROUPS; g++)
        sum += g_attnO[(((long)b * HH + kvh * GROUPS + g) * QN + q) * DD + d];
    __nv_bfloat16 h = __float2bfloat16(sum);
    gXo_hi[i] = h;
    gXo_lo[i] = __float2bfloat16(sum - __bfloat162float(h));
}

// ---------------- launch ----------------
static __nv_bfloat16* sym_addr_b(const void* sym) {
    void* p = nullptr;
    cudaGetSymbolAddress(&p, sym);
    return (__nv_bfloat16*)p;
}
static float* sym_addr_f(const void* sym) {
    void* p = nullptr;
    cudaGetSymbolAddress(&p, sym);
    return (float*)p;
}

extern "C" void kernel_launch(void* const* d_in, const int* in_sizes, int n_in,
                              void* d_out, int out_size)
{
    const float* hidden = (const float*)d_in[0];
    const float* kcache = (const float*)d_in[1];
    const float* vcache = (const float*)d_in[2];
    const float* rope   = (const float*)d_in[3];
    const int*   start  = (const int*)  d_in[5];
    const float* w_qkv  = (const float*)d_in[6];
    const float* w_o    = (const float*)d_in[7];
    const float* qw     = (const float*)d_in[8];
    const float* kw     = (const float*)d_in[9];

    float* out      = (float*)d_out;
    float* out_attn = out;
    float* out_k    = out + OUT_SZ1;
    float* out_v    = out + OUT_SZ1 + CACHE_SZ;

    float* s_qkv = sym_addr_f(g_qkv);
    __nv_bfloat16* sA_hi = sym_addr_b(gA_hi);  __nv_bfloat16* sA_lo = sym_addr_b(gA_lo);
    __nv_bfloat16* sWq_hi = sym_addr_b(gWq_hi); __nv_bfloat16* sWq_lo = sym_addr_b(gWq_lo);
    __nv_bfloat16* sWo_hi = sym_addr_b(gWo_hi); __nv_bfloat16* sWo_lo = sym_addr_b(gWo_lo);
    __nv_bfloat16* sXo_hi = sym_addr_b(gXo_hi); __nv_bfloat16* sXo_lo = sym_addr_b(gXo_lo);

    cudaFuncSetAttribute(gemm_mma, cudaFuncAttributeMaxDynamicSharedMemorySize, GEMM_SMEM);
    cudaFuncSetAttribute(attn_mma, cudaFuncAttributeMaxDynamicSharedMemorySize, ATTN_SMEM);

    // 1. present caches
    cudaMemcpyAsync(out_k, kcache, (size_t)CACHE_SZ * sizeof(float), cudaMemcpyDeviceToDevice, 0);
    cudaMemcpyAsync(out_v, vcache, (size_t)CACHE_SZ * sizeof(float), cudaMemcpyDeviceToDevice, 0);

    // 2. hi/lo conversions (A, weights, PAST region of caches)
    conv_hilo<<<(BB*QN*HID + 255) / 256, 256>>>(hidden, sA_hi, sA_lo, BB*QN*HID);
    conv_hilo_T<<<dim3(NQKV / 32, HID / 32), dim3(32, 8)>>>(w_qkv, sWq_hi, sWq_lo, HID, NQKV);
    conv_hilo_T<<<dim3(HID / 32, (HKV*DD) / 32), dim3(32, 8)>>>(w_o, sWo_hi, sWo_lo, HKV*DD, HID);
    kv_hilo_past<<<(BB*HKV*PAST*DD + 255) / 256, 256>>>(kcache, vcache);

    // 3. QKV projection
    gemm_mma<<<dim3(NQKV / 128, (BB*QN) / 128), 128, GEMM_SMEM>>>(
        sA_hi, sA_lo, sWq_hi, sWq_lo, s_qkv, BB*QN, NQKV, HID);

    // 4. RMSNorm + RoPE + scatter + fused Q/K/V hi/lo
    qkv_post_kernel<<<dim3(48, QN, BB), 128>>>(rope, start, qw, kw, out_k, out_v);

    // 5. tensor-core flash attention (2 heads per CTA)
    attn_mma<<<dim3(QN / 64, HH / 2, BB), 256, ATTN_SMEM>>>();

    // 6. group-sum + hi/lo
    group_sum_kernel<<<(BB*QN*HKV*DD + 255) / 256, 256>>>();

    // 7. output projection
    gemm_mma<<<dim3(HID / 128, (BB*QN) / 128), 128, GEMM_SMEM>>>(
        sXo_hi, sXo_lo, sWo_hi, sWo_lo, out_attn, BB*QN, HID, HKV*DD);
}

// round 9
// speedup vs baseline: 1.0259x; 1.0259x over previous
#include <cuda_runtime.h>
#include <cuda_bf16.h>
#include <cstdint>

// ---------------- problem constants ----------------
#define BB    2
#define QN    1024
#define PAST  1024
#define MAXC  4096
#define HH    32
#define HKV   8
#define DD    128
#define HID   4096
#define KLEN  (PAST + QN)          // 2048
#define NQKV  ((HH + 2*HKV) * DD)  // 6144
#define GROUPS (HH / HKV)
#define SCALE 0.08838834764831845f

#define OUT_SZ1 (BB*QN*HID)
#define CACHE_SZ (BB*HKV*MAXC*DD)

// ---------------- scratch (device globals) ----------------
__device__ __align__(16) float g_qkv  [BB*QN*NQKV];
__device__ __align__(16) float g_attnO[BB*HH*QN*DD];

__device__ __align__(16) __nv_bfloat16 gA_hi [BB*QN*HID];
__device__ __align__(16) __nv_bfloat16 gA_lo [BB*QN*HID];
__device__ __align__(16) __nv_bfloat16 gWq_hi[NQKV*HID];
__device__ __align__(16) __nv_bfloat16 gWq_lo[NQKV*HID];
__device__ __align__(16) __nv_bfloat16 gWo_hi[HID*HKV*DD];
__device__ __align__(16) __nv_bfloat16 gWo_lo[HID*HKV*DD];
__device__ __align__(16) __nv_bfloat16 gXo_hi[BB*QN*HKV*DD];
__device__ __align__(16) __nv_bfloat16 gXo_lo[BB*QN*HKV*DD];

// attention bf16 hi/lo operands
__device__ __align__(16) __nv_bfloat16 gQ_hi [BB*HH*QN*DD];
__device__ __align__(16) __nv_bfloat16 gQ_lo [BB*HH*QN*DD];
__device__ __align__(16) __nv_bfloat16 gKc_hi[BB*HKV*KLEN*DD];
__device__ __align__(16) __nv_bfloat16 gKc_lo[BB*HKV*KLEN*DD];
__device__ __align__(16) __nv_bfloat16 gVc_hi[BB*HKV*KLEN*DD];
__device__ __align__(16) __nv_bfloat16 gVc_lo[BB*HKV*KLEN*DD];

// ================= PTX helpers (sm_80+ portable subset) =================
__device__ __forceinline__ uint32_t smem_u32(const void* p) {
    uint32_t a;
    asm("{ .reg .u64 t; cvta.to.shared.u64 t, %1; cvt.u32.u64 %0, t; }" : "=r"(a) : "l"(p));
    return a;
}
__device__ __forceinline__ void ldm_x4(uint32_t* r, uint32_t addr) {
    asm volatile("ldmatrix.sync.aligned.m8n8.x4.shared.b16 {%0,%1,%2,%3}, [%4];"
                 : "=r"(r[0]), "=r"(r[1]), "=r"(r[2]), "=r"(r[3]) : "r"(addr));
}
__device__ __forceinline__ void ldm_x4t(uint32_t* r, uint32_t addr) {
    asm volatile("ldmatrix.sync.aligned.m8n8.x4.trans.shared.b16 {%0,%1,%2,%3}, [%4];"
                 : "=r"(r[0]), "=r"(r[1]), "=r"(r[2]), "=r"(r[3]) : "r"(addr));
}
__device__ __forceinline__ void mma_bf16(float* d, const uint32_t* a, const uint32_t* b) {
    asm volatile(
        "mma.sync.aligned.m16n8k16.row.col.f32.bf16.bf16.f32 "
        "{%0,%1,%2,%3}, {%4,%5,%6,%7}, {%8,%9}, {%0,%1,%2,%3};"
        : "+f"(d[0]), "+f"(d[1]), "+f"(d[2]), "+f"(d[3])
        : "r"(a[0]), "r"(a[1]), "r"(a[2]), "r"(a[3]), "r"(b[0]), "r"(b[1]));
}
__device__ __forceinline__ void cp16(uint32_t dst, const void* src) {
    asm volatile("cp.async.cg.shared.global [%0], [%1], 16;" :: "r"(dst), "l"(src));
}
__device__ __forceinline__ uint32_t pack_bf2(float x, float y) {
    __nv_bfloat162 h;
    h.x = __float2bfloat16(x); h.y = __float2bfloat16(y);
    return *(uint32_t*)&h;
}

// ================= hi/lo conversion kernels =================
__global__ void conv_hilo(const float* __restrict__ src,
                          __nv_bfloat16* __restrict__ hi, __nv_bfloat16* __restrict__ lo, int n) {
    int i = blockIdx.x * 256 + threadIdx.x;
    if (i >= n) return;
    float x = src[i];
    __nv_bfloat16 h = __float2bfloat16(x);
    hi[i] = h;
    lo[i] = __float2bfloat16(x - __bfloat162float(h));
}

// src [K][N] fp32 -> hi/lo [N][K] bf16
__global__ void conv_hilo_T(const float* __restrict__ src,
                            __nv_bfloat16* __restrict__ hi, __nv_bfloat16* __restrict__ lo,
                            int K, int N) {
    __shared__ float t[32][33];
    int bn = blockIdx.x * 32, bk = blockIdx.y * 32;
    int x = threadIdx.x, y = threadIdx.y;
    #pragma unroll
    for (int i = 0; i < 32; i += 8)
        t[y + i][x] = src[(long)(bk + y + i) * N + bn + x];
    __syncthreads();
    #pragma unroll
    for (int i = 0; i < 32; i += 8) {
        float v = t[x][y + i];
        long o = (long)(bn + y + i) * K + bk + x;
        __nv_bfloat16 h = __float2bfloat16(v);
        hi[o] = h;
        lo[o] = __float2bfloat16(v - __bfloat162float(h));
    }
}

// PAST rows of the caches -> hi/lo (reads original input caches)
__global__ void kv_hilo_past(const float* __restrict__ kc, const float* __restrict__ vc) {
    long i = (long)blockIdx.x * 256 + threadIdx.x;
    if (i >= (long)BB * HKV * PAST * DD) return;
    int d = (int)(i & (DD - 1));
    long t = i >> 7;
    int pos = (int)(t & (PAST - 1));
    t >>= 10;                               // t = b*HKV + h
    long src = (t * MAXC + pos) * DD + d;
    long dst = (t * KLEN + pos) * DD + d;
    float kx = kc[src];
    __nv_bfloat16 kh = __float2bfloat16(kx);
    gKc_hi[dst] = kh;
    gKc_lo[dst] = __float2bfloat16(kx - __bfloat162float(kh));
    float vx = vc[src];
    __nv_bfloat16 vh = __float2bfloat16(vx);
    gVc_hi[dst] = vh;
    gVc_lo[dst] = __float2bfloat16(vx - __bfloat162float(vh));
}

// ================= warp-MMA hi/lo GEMM (3-stage, swizzled, 64x64 warp tile) =================
#define TILE_B  8192
#define STAGE_B (4 * TILE_B)              // Ahi,Alo,Bhi,Blo = 32768
#define NST     3
#define GEMM_SMEM (NST * STAGE_B)         // 98304

__device__ __forceinline__ uint32_t swz(int row, int ch) {
    return (uint32_t)(row * 64 + ((ch ^ ((row >> 1) & 3)) << 4));
}

__device__ __forceinline__ void fill_stage(
    uint32_t sb, int kt, int m0, int n0, int K,
    const __nv_bfloat16* Ahi, const __nv_bfloat16* Alo,
    const __nv_bfloat16* Bhi, const __nv_bfloat16* Blo, int tid)
{
    long k0 = (long)kt * 32;
    const __nv_bfloat16* bases[4] = {Ahi, Alo, Bhi, Blo};
    #pragma unroll
    for (int t = 0; t < 4; t++) {
        const __nv_bfloat16* bp = bases[t];
        int r0 = (t < 2) ? m0 : n0;
        #pragma unroll
        for (int i = 0; i < 4; i++) {
            int idx = tid + i * 128;
            int row = idx >> 2, ch = idx & 3;
            cp16(sb + t * TILE_B + swz(row, ch), bp + (long)(r0 + row) * K + k0 + ch * 8);
        }
    }
}

__global__ void __launch_bounds__(128, 2) gemm_mma(
    const __nv_bfloat16* __restrict__ Ahi, const __nv_bfloat16* __restrict__ Alo,
    const __nv_bfloat16* __restrict__ Bhi, const __nv_bfloat16* __restrict__ Blo,
    float* __restrict__ C, int M, int N, int K)
{
    extern __shared__ char smraw[];
    uint32_t s0 = smem_u32(smraw);
    int tid = threadIdx.x, lane = tid & 31, wid = tid >> 5;
    int wm = wid & 1, wn = wid >> 1;
    int m0 = blockIdx.y * 128, n0 = blockIdx.x * 128;

    float acc[4][8][4];
    #pragma unroll
    for (int i = 0; i < 4; i++)
        #pragma unroll
        for (int j = 0; j < 8; j++)
            #pragma unroll
            for (int k = 0; k < 4; k++) acc[i][j][k] = 0.f;

    int nk = K >> 5;
    fill_stage(s0, 0, m0, n0, K, Ahi, Alo, Bhi, Blo, tid);
    asm volatile("cp.async.commit_group;" ::: "memory");
    fill_stage(s0 + STAGE_B, 1, m0, n0, K, Ahi, Alo, Bhi, Blo, tid);
    asm volatile("cp.async.commit_group;" ::: "memory");

    int a_row = wm * 64 + (lane & 15);
    int a_cb  = lane >> 4;
    int b_row = wn * 64 + (lane & 7) + (lane >> 4) * 8;
    int b_cb  = (lane >> 3) & 1;

    for (int kt = 0; kt < nk; kt++) {
        asm volatile("cp.async.wait_group 1;" ::: "memory");
        __syncthreads();

        if (kt + 2 < nk)
            fill_stage(s0 + ((kt + 2) % NST) * STAGE_B, kt + 2, m0, n0, K, Ahi, Alo, Bhi, Blo, tid);
        asm volatile("cp.async.commit_group;" ::: "memory");

        uint32_t sb = s0 + (kt % NST) * STAGE_B;
        #pragma unroll
        for (int ks = 0; ks < 2; ks++) {
            uint32_t a[2][4][4];
            #pragma unroll
            for (int hl = 0; hl < 2; hl++)
                #pragma unroll
                for (int mt = 0; mt < 4; mt++)
                    ldm_x4(a[hl][mt], sb + hl * TILE_B + swz(a_row + mt * 16, ks * 2 + a_cb));
            #pragma unroll
            for (int np = 0; np < 4; np++) {
                uint32_t bh[4], bl[4];
                uint32_t bo = swz(b_row + np * 16, ks * 2 + b_cb);
                ldm_x4(bh, sb + 2 * TILE_B + bo);
                ldm_x4(bl, sb + 3 * TILE_B + bo);
                #pragma unroll
                for (int mt = 0; mt < 4; mt++)
                    #pragma unroll
                    for (int nt = 0; nt < 2; nt++) {
                        float* d = acc[mt][np * 2 + nt];
                        mma_bf16(d, a[0][mt], &bh[nt * 2]);
                        mma_bf16(d, a[0][mt], &bl[nt * 2]);
                        mma_bf16(d, a[1][mt], &bh[nt * 2]);
                    }
            }
        }
    }

    int row0 = m0 + wm * 64 + (lane >> 2);
    int col0 = n0 + wn * 64 + (lane & 3) * 2;
    #pragma unroll
    for (int mt = 0; mt < 4; mt++)
        #pragma unroll
        for (int nt = 0; nt < 8; nt++) {
            float* d = acc[mt][nt];
            long r = row0 + mt * 16;
            long c = col0 + nt * 8;
            *(float2*)(C + r * N + c)       = make_float2(d[0], d[1]);
            *(float2*)(C + (r + 8) * N + c) = make_float2(d[2], d[3]);
        }
}

// ---------------- RMSNorm + RoPE + scatter + fused hi/lo emission ----------------
__global__ void qkv_post_kernel(const float* __restrict__ rope,
                                const int*   __restrict__ start,
                                const float* __restrict__ qw,
                                const float* __restrict__ kw,
                                float* __restrict__ out_k,
                                float* __restrict__ out_v)
{
    int slot = blockIdx.x;
    int q    = blockIdx.y;
    int b    = blockIdx.z;
    int tid  = threadIdx.x;
    long row = ((long)b * QN + q) * NQKV;
    float x = g_qkv[row + (long)slot * DD + tid];
    int pos = start[b] + q;

    if (slot >= 40) {  // V: raw scatter + hi/lo
        int h = slot - 40;
        out_v[(((long)b * HKV + h) * MAXC + pos) * DD + tid] = x;
        long vi = (((long)b * HKV + h) * KLEN + pos) * DD + tid;
        __nv_bfloat16 vh = __float2bfloat16(x);
        gVc_hi[vi] = vh;
        gVc_lo[vi] = __float2bfloat16(x - __bfloat162float(vh));
        return;
    }

    __shared__ float red[4];
    __shared__ float sm[DD];
    float v2 = x * x;
    #pragma unroll
    for (int m = 16; m; m >>= 1) v2 += __shfl_xor_sync(0xffffffffu, v2, m);
    if ((tid & 31) == 0) red[tid >> 5] = v2;
    __syncthreads();
    float tot = red[0] + red[1] + red[2] + red[3];
    float scl = rsqrtf(tot * (1.f / DD) + 1e-6f);
    const float* w = (slot < 32) ? qw : kw;
    sm[tid] = x * scl * w[tid];
    __syncthreads();

    int i = (tid < 64) ? tid : tid - 64;
    float c = rope[(long)pos * DD + i];
    float s = rope[(long)pos * DD + 64 + i];
    float x1 = sm[i], x2 = sm[i + 64];
    float o = (tid < 64) ? (x1 * c - x2 * s) : (x2 * c + x1 * s);

    if (slot < 32) {   // Q: scaled hi/lo
        float xs = o * SCALE;
        long qi = (((long)b * HH + slot) * QN + q) * DD + tid;
        __nv_bfloat16 qh = __float2bfloat16(xs);
        gQ_hi[qi] = qh;
        gQ_lo[qi] = __float2bfloat16(xs - __bfloat162float(qh));
    } else {           // K: fp32 scatter + hi/lo
        int h = slot - 32;
        out_k[(((long)b * HKV + h) * MAXC + pos) * DD + tid] = o;
        long ki = (((long)b * HKV + h) * KLEN + pos) * DD + tid;
        __nv_bfloat16 kh = __float2bfloat16(o);
        gKc_hi[ki] = kh;
        gKc_lo[ki] = __float2bfloat16(o - __bfloat162float(kh));
    }
}

// ================= tensor-core flash attention (bf16 hi/lo, R7 shape) =================
#define APITCHB 272
#define AQ 64
#define ATILE (AQ * APITCHB)               // 17408 per hi or lo
#define ATTN_SMEM (6 * ATILE)              // 104448

__device__ __forceinline__ void load_tile64(uint32_t dst,
    const __nv_bfloat16* hi, const __nv_bfloat16* lo, long rowbase, int tid)
{
    #pragma unroll
    for (int i = 0; i < 8; i++) {
        int idx = tid + i * 128;
        int row = idx >> 4, ch = idx & 15;
        uint32_t d = dst + row * APITCHB + ch * 16;
        const long off = rowbase + (long)row * DD + (ch << 3);
        cp16(d, hi + off);
        cp16(d + ATILE, lo + off);
    }
}

__global__ void __launch_bounds__(128, 2) attn_mma()
{
    extern __shared__ char smraw[];
    uint32_t sQ = smem_u32(smraw);
    uint32_t sK = sQ + 2 * ATILE;
    uint32_t sV = sK + 2 * ATILE;
    int tid = threadIdx.x, lane = tid & 31, w = tid >> 5;
    int qt = blockIdx.x, h = blockIdx.y, b = blockIdx.z;
    int kvh = h >> 2;
    int q0 = qt * 64;

    long qbase  = ((long)(b * HH + h) * QN + q0) * DD;
    long kvbase = (long)(b * HKV + kvh) * KLEN * DD;

    load_tile64(sQ, gQ_hi, gQ_lo, qbase, tid);
    load_tile64(sK, gKc_hi, gKc_lo, kvbase, tid);
    asm volatile("cp.async.commit_group;" ::: "memory");

    const int nc = 17 + qt;

    float O[16][4];
    #pragma unroll
    for (int i = 0; i < 16; i++)
        #pragma unroll
        for (int j = 0; j < 4; j++) O[i][j] = 0.f;
    float m0 = -1e30f, m1 = -1e30f, l0 = 0.f, l1 = 0.f;

    const int a_row  = w * 16 + (lane & 15);
    const int a_kb   = (lane >> 4) * 16;
    const int b_row  = (lane & 7) + (lane >> 4) * 8;
    const int b_kb   = ((lane >> 3) & 1) * 16;
    const int v_row  = lane & 15;
    const int v_col  = (lane >> 4) * 8;

    for (int c = 0; c < nc; c++) {
        int kb = c * 64;
        asm volatile("cp.async.wait_group 0;" ::: "memory");
        __syncthreads();

        load_tile64(sV, gVc_hi, gVc_lo, kvbase + (long)kb * DD, tid);
        asm volatile("cp.async.commit_group;" ::: "memory");

        // ---- S = Q K^T ----
        float S[8][4];
        #pragma unroll
        for (int j = 0; j < 8; j++)
            #pragma unroll
            for (int k = 0; k < 4; k++) S[j][k] = 0.f;

        #pragma unroll
        for (int ks = 0; ks < 8; ks++) {
            uint32_t ah[4], al[4];
            uint32_t qa = sQ + a_row * APITCHB + ks * 32 + a_kb;
            ldm_x4(ah, qa);
            ldm_x4(al, qa + ATILE);
            #pragma unroll
            for (int np = 0; np < 4; np++) {
                uint32_t bh[4], bl[4];
                uint32_t ka = sK + (np * 16 + b_row) * APITCHB + ks * 32 + b_kb;
                ldm_x4(bh, ka);
                ldm_x4(bl, ka + ATILE);
                #pragma unroll
                for (int nt = 0; nt < 2; nt++) {
                    float* d = S[np * 2 + nt];
                    mma_bf16(d, ah, &bh[nt * 2]);
                    mma_bf16(d, ah, &bl[nt * 2]);
                    mma_bf16(d, al, &bh[nt * 2]);
                }
            }
        }

        if (c == nc - 1) {
            int klim0 = PAST + q0 + w * 16 + (lane >> 2);
            int klim1 = klim0 + 8;
            #pragma unroll
            for (int j = 0; j < 8; j++) {
                int col = kb + j * 8 + (lane & 3) * 2;
                if (col > klim0)     S[j][0] = -1e30f;
                if (col + 1 > klim0) S[j][1] = -1e30f;
                if (col > klim1)     S[j][2] = -1e30f;
                if (col + 1 > klim1) S[j][3] = -1e30f;
            }
        }

        // ---- online softmax ----
        float mx0 = -1e30f, mx1 = -1e30f;
        #pragma unroll
        for (int j = 0; j < 8; j++) {
            mx0 = fmaxf(mx0, fmaxf(S[j][0], S[j][1]));
            mx1 = fmaxf(mx1, fmaxf(S[j][2], S[j][3]));
        }
        mx0 = fmaxf(mx0, __shfl_xor_sync(0xffffffffu, mx0, 1));
        mx0 = fmaxf(mx0, __shfl_xor_sync(0xffffffffu, mx0, 2));
        mx1 = fmaxf(mx1, __shfl_xor_sync(0xffffffffu, mx1, 1));
        mx1 = fmaxf(mx1, __shfl_xor_sync(0xffffffffu, mx1, 2));
        float mn0 = fmaxf(m0, mx0), mn1 = fmaxf(m1, mx1);
        float al0 = __expf(m0 - mn0), al1 = __expf(m1 - mn1);
        float r0 = 0.f, r1 = 0.f;
        #pragma unroll
        for (int j = 0; j < 8; j++) {
            S[j][0] = __expf(S[j][0] - mn0);
            S[j][1] = __expf(S[j][1] - mn0);
            S[j][2] = __expf(S[j][2] - mn1);
            S[j][3] = __expf(S[j][3] - mn1);
            r0 += S[j][0] + S[j][1];
            r1 += S[j][2] + S[j][3];
        }
        r0 += __shfl_xor_sync(0xffffffffu, r0, 1);
        r0 += __shfl_xor_sync(0xffffffffu, r0, 2);
        r1 += __shfl_xor_sync(0xffffffffu, r1, 1);
        r1 += __shfl_xor_sync(0xffffffffu, r1, 2);
        l0 = l0 * al0 + r0;
        l1 = l1 * al1 + r1;
        m0 = mn0; m1 = mn1;
        #pragma unroll
        for (int i = 0; i < 16; i++) {
            O[i][0] *= al0; O[i][1] *= al0;
            O[i][2] *= al1; O[i][3] *= al1;
        }

        // ---- P -> bf16 hi/lo A-frags ----
        uint32_t pa_h[4][4], pa_l[4][4];
        #pragma unroll
        for (int kt = 0; kt < 4; kt++) {
            int j0 = 2 * kt, j1 = 2 * kt + 1;
            float v00 = S[j0][0], v01 = S[j0][1], v02 = S[j0][2], v03 = S[j0][3];
            float v10 = S[j1][0], v11 = S[j1][1], v12 = S[j1][2], v13 = S[j1][3];
            pa_h[kt][0] = pack_bf2(v00, v01);
            pa_h[kt][1] = pack_bf2(v02, v03);
            pa_h[kt][2] = pack_bf2(v10, v11);
            pa_h[kt][3] = pack_bf2(v12, v13);
            __nv_bfloat162* hp;
            hp = (__nv_bfloat162*)&pa_h[kt][0];
            pa_l[kt][0] = pack_bf2(v00 - __bfloat162float(hp->x), v01 - __bfloat162float(hp->y));
            hp = (__nv_bfloat162*)&pa_h[kt][1];
            pa_l[kt][1] = pack_bf2(v02 - __bfloat162float(hp->x), v03 - __bfloat162float(hp->y));
            hp = (__nv_bfloat162*)&pa_h[kt][2];
            pa_l[kt][2] = pack_bf2(v10 - __bfloat162float(hp->x), v11 - __bfloat162float(hp->y));
            hp = (__nv_bfloat162*)&pa_h[kt][3];
            pa_l[kt][3] = pack_bf2(v12 - __bfloat162float(hp->x), v13 - __bfloat162float(hp->y));
        }

        __syncthreads();
        if (c + 1 < nc) {
            load_tile64(sK, gKc_hi, gKc_lo, kvbase + (long)(kb + 64) * DD, tid);
            asm volatile("cp.async.commit_group;" ::: "memory");
            asm volatile("cp.async.wait_group 1;" ::: "memory");
        } else {
            asm volatile("cp.async.wait_group 0;" ::: "memory");
        }
        __syncthreads();

        // ---- O += P V ----
        #pragma unroll
        for (int kt = 0; kt < 4; kt++) {
            #pragma unroll
            for (int np = 0; np < 8; np++) {
                uint32_t vh[4], vl[4];
                uint32_t va = sV + (kt * 16 + v_row) * APITCHB + (np * 16 + v_col) * 2;
                ldm_x4t(vh, va);
                ldm_x4t(vl, va + ATILE);
                #pragma unroll
                for (int nt = 0; nt < 2; nt++) {
                    float* d = O[np * 2 + nt];
                    mma_bf16(d, pa_h[kt], &vh[nt * 2]);
                    mma_bf16(d, pa_h[kt], &vl[nt * 2]);
                    mma_bf16(d, pa_l[kt], &vh[nt * 2]);
                }
            }
        }
        __syncthreads();
    }

    float inv0 = 1.f / l0, inv1 = 1.f / l1;
    int row0 = q0 + w * 16 + (lane >> 2);
    float* ob = g_attnO + ((long)(b * HH + h) * QN) * DD;
    #pragma unroll
    for (int np = 0; np < 16; np++) {
        int col = np * 8 + (lane & 3) * 2;
        *(float2*)(ob + (long)row0 * DD + col)       = make_float2(O[np][0] * inv0, O[np][1] * inv0);
        *(float2*)(ob + (long)(row0 + 8) * DD + col) = make_float2(O[np][2] * inv1, O[np][3] * inv1);
    }
}

// ---------------- group sum + hi/lo conversion ----------------
__global__ void group_sum_kernel()
{
    long i = (long)blockIdx.x * 256 + threadIdx.x;
    if (i >= (long)BB * QN * HKV * DD) return;
    int d = (int)(i & (DD - 1));
    long t = i >> 7;
    int kvh = (int)(t & (HKV - 1));
    t >>= 3;
    int q = (int)(t % QN);
    int b = (int)(t / QN);
    float sum = 0.f;
    #pragma unroll
    for (int g = 0; g < GROUPS; g++)
        sum += g_attnO[(((long)b * HH + kvh * GROUPS + g) * QN + q) * DD + d];
    __nv_bfloat16 h = __float2bfloat16(sum);
    gXo_hi[i] = h;
    gXo_lo[i] = __float2bfloat16(sum - __bfloat162float(h));
}

// ---------------- launch ----------------
static __nv_bfloat16* sym_addr_b(const void* sym) {
    void* p = nullptr;
    cudaGetSymbolAddress(&p, sym);
    return (__nv_bfloat16*)p;
}
static float* sym_addr_f(const void* sym) {
    void* p = nullptr;
    cudaGetSymbolAddress(&p, sym);
    return (float*)p;
}

extern "C" void kernel_launch(void* const* d_in, const int* in_sizes, int n_in,
                              void* d_out, int out_size)
{
    const float* hidden = (const float*)d_in[0];
    const float* kcache = (const float*)d_in[1];
    const float* vcache = (const float*)d_in[2];
    const float* rope   = (const float*)d_in[3];
    const int*   start  = (const int*)  d_in[5];
    const float* w_qkv  = (const float*)d_in[6];
    const float* w_o    = (const float*)d_in[7];
    const float* qw     = (const float*)d_in[8];
    const float* kw     = (const float*)d_in[9];

    float* out      = (float*)d_out;
    float* out_attn = out;
    float* out_k    = out + OUT_SZ1;
    float* out_v    = out + OUT_SZ1 + CACHE_SZ;

    float* s_qkv = sym_addr_f(g_qkv);
    __nv_bfloat16* sA_hi = sym_addr_b(gA_hi);  __nv_bfloat16* sA_lo = sym_addr_b(gA_lo);
    __nv_bfloat16* sWq_hi = sym_addr_b(gWq_hi); __nv_bfloat16* sWq_lo = sym_addr_b(gWq_lo);
    __nv_bfloat16* sWo_hi = sym_addr_b(gWo_hi); __nv_bfloat16* sWo_lo = sym_addr_b(gWo_lo);
    __nv_bfloat16* sXo_hi = sym_addr_b(gXo_hi); __nv_bfloat16* sXo_lo = sym_addr_b(gXo_lo);

    cudaFuncSetAttribute(gemm_mma, cudaFuncAttributeMaxDynamicSharedMemorySize, GEMM_SMEM);
    cudaFuncSetAttribute(attn_mma, cudaFuncAttributeMaxDynamicSharedMemorySize, ATTN_SMEM);

    // 1. present caches
    cudaMemcpyAsync(out_k, kcache, (size_t)CACHE_SZ * sizeof(float), cudaMemcpyDeviceToDevice, 0);
    cudaMemcpyAsync(out_v, vcache, (size_t)CACHE_SZ * sizeof(float), cudaMemcpyDeviceToDevice, 0);

    // 2. hi/lo conversions (A, weights, PAST region of caches)
    conv_hilo<<<(BB*QN*HID + 255) / 256, 256>>>(hidden, sA_hi, sA_lo, BB*QN*HID);
    conv_hilo_T<<<dim3(NQKV / 32, HID / 32), dim3(32, 8)>>>(w_qkv, sWq_hi, sWq_lo, HID, NQKV);
    conv_hilo_T<<<dim3(HID / 32, (HKV*DD) / 32), dim3(32, 8)>>>(w_o, sWo_hi, sWo_lo, HKV*DD, HID);
    kv_hilo_past<<<(BB*HKV*PAST*DD + 255) / 256, 256>>>(kcache, vcache);

    // 3. QKV projection
    gemm_mma<<<dim3(NQKV / 128, (BB*QN) / 128), 128, GEMM_SMEM>>>(
        sA_hi, sA_lo, sWq_hi, sWq_lo, s_qkv, BB*QN, NQKV, HID);

    // 4. RMSNorm + RoPE + scatter + fused Q/K/V hi/lo
    qkv_post_kernel<<<dim3(48, QN, BB), 128>>>(rope, start, qw, kw, out_k, out_v);

    // 5. tensor-core flash attention (R7 shape: 64q/CTA, 4 warps, 2 CTA/SM)
    attn_mma<<<dim3(QN / 64, HH, BB), 128, ATTN_SMEM>>>();

    // 6. group-sum + hi/lo
    group_sum_kernel<<<(BB*QN*HKV*DD + 255) / 256, 256>>>();

    // 7. output projection
    gemm_mma<<<dim3(HID / 128, (BB*QN) / 128), 128, GEMM_SMEM>>>(
        sXo_hi, sXo_lo, sWo_hi, sWo_lo, out_attn, BB*QN, HID, HKV*DD);
}

// round 10
// speedup vs baseline: 1.0720x; 1.0449x over previous
#include <cuda_runtime.h>
#include <cuda_bf16.h>
#include <cstdint>

// ---------------- problem constants ----------------
#define BB    2
#define QN    1024
#define PAST  1024
#define MAXC  4096
#define HH    32
#define HKV   8
#define DD    128
#define HID   4096
#define KLEN  (PAST + QN)          // 2048
#define NQKV  ((HH + 2*HKV) * DD)  // 6144
#define GROUPS (HH / HKV)
#define SCALE 0.08838834764831845f
#define LOG2E 1.4426950408889634f

#define OUT_SZ1 (BB*QN*HID)
#define CACHE_SZ (BB*HKV*MAXC*DD)

// ---------------- scratch (device globals) ----------------
__device__ __align__(16) float g_qkv  [BB*QN*NQKV];
__device__ __align__(16) float g_attnO[BB*HH*QN*DD];

__device__ __align__(16) __nv_bfloat16 gA_hi [BB*QN*HID];
__device__ __align__(16) __nv_bfloat16 gA_lo [BB*QN*HID];
__device__ __align__(16) __nv_bfloat16 gWq_hi[NQKV*HID];
__device__ __align__(16) __nv_bfloat16 gWq_lo[NQKV*HID];
__device__ __align__(16) __nv_bfloat16 gWo_hi[HID*HKV*DD];
__device__ __align__(16) __nv_bfloat16 gWo_lo[HID*HKV*DD];
__device__ __align__(16) __nv_bfloat16 gXo_hi[BB*QN*HKV*DD];
__device__ __align__(16) __nv_bfloat16 gXo_lo[BB*QN*HKV*DD];

// attention bf16 hi/lo operands (Q pre-scaled by SCALE*LOG2E)
__device__ __align__(16) __nv_bfloat16 gQ_hi [BB*HH*QN*DD];
__device__ __align__(16) __nv_bfloat16 gQ_lo [BB*HH*QN*DD];
__device__ __align__(16) __nv_bfloat16 gKc_hi[BB*HKV*KLEN*DD];
__device__ __align__(16) __nv_bfloat16 gKc_lo[BB*HKV*KLEN*DD];
__device__ __align__(16) __nv_bfloat16 gVc_hi[BB*HKV*KLEN*DD];
__device__ __align__(16) __nv_bfloat16 gVc_lo[BB*HKV*KLEN*DD];

// ================= PTX helpers (sm_80+ portable subset) =================
__device__ __forceinline__ uint32_t smem_u32(const void* p) {
    uint32_t a;
    asm("{ .reg .u64 t; cvta.to.shared.u64 t, %1; cvt.u32.u64 %0, t; }" : "=r"(a) : "l"(p));
    return a;
}
__device__ __forceinline__ void ldm_x4(uint32_t* r, uint32_t addr) {
    asm volatile("ldmatrix.sync.aligned.m8n8.x4.shared.b16 {%0,%1,%2,%3}, [%4];"
                 : "=r"(r[0]), "=r"(r[1]), "=r"(r[2]), "=r"(r[3]) : "r"(addr));
}
__device__ __forceinline__ void ldm_x4t(uint32_t* r, uint32_t addr) {
    asm volatile("ldmatrix.sync.aligned.m8n8.x4.trans.shared.b16 {%0,%1,%2,%3}, [%4];"
                 : "=r"(r[0]), "=r"(r[1]), "=r"(r[2]), "=r"(r[3]) : "r"(addr));
}
__device__ __forceinline__ void mma_bf16(float* d, const uint32_t* a, const uint32_t* b) {
    asm volatile(
        "mma.sync.aligned.m16n8k16.row.col.f32.bf16.bf16.f32 "
        "{%0,%1,%2,%3}, {%4,%5,%6,%7}, {%8,%9}, {%0,%1,%2,%3};"
        : "+f"(d[0]), "+f"(d[1]), "+f"(d[2]), "+f"(d[3])
        : "r"(a[0]), "r"(a[1]), "r"(a[2]), "r"(a[3]), "r"(b[0]), "r"(b[1]));
}
__device__ __forceinline__ void cp16(uint32_t dst, const void* src) {
    asm volatile("cp.async.cg.shared.global [%0], [%1], 16;" :: "r"(dst), "l"(src));
}
__device__ __forceinline__ uint32_t pack_bf2(float x, float y) {
    __nv_bfloat162 h;
    h.x = __float2bfloat16(x); h.y = __float2bfloat16(y);
    return *(uint32_t*)&h;
}
__device__ __forceinline__ float ex2(float x) {
    float y;
    asm("ex2.approx.f32 %0, %1;" : "=f"(y) : "f"(x));
    return y;
}

// ================= hi/lo conversion kernels =================
__global__ void conv_hilo(const float* __restrict__ src,
                          __nv_bfloat16* __restrict__ hi, __nv_bfloat16* __restrict__ lo, int n) {
    int i = blockIdx.x * 256 + threadIdx.x;
    if (i >= n) return;
    float x = src[i];
    __nv_bfloat16 h = __float2bfloat16(x);
    hi[i] = h;
    lo[i] = __float2bfloat16(x - __bfloat162float(h));
}

// src [K][N] fp32 -> hi/lo [N][K] bf16
__global__ void conv_hilo_T(const float* __restrict__ src,
                            __nv_bfloat16* __restrict__ hi, __nv_bfloat16* __restrict__ lo,
                            int K, int N) {
    __shared__ float t[32][33];
    int bn = blockIdx.x * 32, bk = blockIdx.y * 32;
    int x = threadIdx.x, y = threadIdx.y;
    #pragma unroll
    for (int i = 0; i < 32; i += 8)
        t[y + i][x] = src[(long)(bk + y + i) * N + bn + x];
    __syncthreads();
    #pragma unroll
    for (int i = 0; i < 32; i += 8) {
        float v = t[x][y + i];
        long o = (long)(bn + y + i) * K + bk + x;
        __nv_bfloat16 h = __float2bfloat16(v);
        hi[o] = h;
        lo[o] = __float2bfloat16(v - __bfloat162float(h));
    }
}

// PAST rows of the caches -> hi/lo (reads original input caches)
__global__ void kv_hilo_past(const float* __restrict__ kc, const float* __restrict__ vc) {
    long i = (long)blockIdx.x * 256 + threadIdx.x;
    if (i >= (long)BB * HKV * PAST * DD) return;
    int d = (int)(i & (DD - 1));
    long t = i >> 7;
    int pos = (int)(t & (PAST - 1));
    t >>= 10;                               // t = b*HKV + h
    long src = (t * MAXC + pos) * DD + d;
    long dst = (t * KLEN + pos) * DD + d;
    float kx = kc[src];
    __nv_bfloat16 kh = __float2bfloat16(kx);
    gKc_hi[dst] = kh;
    gKc_lo[dst] = __float2bfloat16(kx - __bfloat162float(kh));
    float vx = vc[src];
    __nv_bfloat16 vh = __float2bfloat16(vx);
    gVc_hi[dst] = vh;
    gVc_lo[dst] = __float2bfloat16(vx - __bfloat162float(vh));
}

// ================= warp-MMA hi/lo GEMM (3-stage, swizzled, 64x64 warp tile) =================
#define TILE_B  8192
#define STAGE_B (4 * TILE_B)              // Ahi,Alo,Bhi,Blo = 32768
#define NST     3
#define GEMM_SMEM (NST * STAGE_B)         // 98304

__device__ __forceinline__ uint32_t swz(int row, int ch) {
    return (uint32_t)(row * 64 + ((ch ^ ((row >> 1) & 3)) << 4));
}

__device__ __forceinline__ void fill_stage(
    uint32_t sb, int kt, int m0, int n0, int K,
    const __nv_bfloat16* Ahi, const __nv_bfloat16* Alo,
    const __nv_bfloat16* Bhi, const __nv_bfloat16* Blo, int tid)
{
    long k0 = (long)kt * 32;
    const __nv_bfloat16* bases[4] = {Ahi, Alo, Bhi, Blo};
    #pragma unroll
    for (int t = 0; t < 4; t++) {
        const __nv_bfloat16* bp = bases[t];
        int r0 = (t < 2) ? m0 : n0;
        #pragma unroll
        for (int i = 0; i < 4; i++) {
            int idx = tid + i * 128;
            int row = idx >> 2, ch = idx & 3;
            cp16(sb + t * TILE_B + swz(row, ch), bp + (long)(r0 + row) * K + k0 + ch * 8);
        }
    }
}

__global__ void __launch_bounds__(128, 2) gemm_mma(
    const __nv_bfloat16* __restrict__ Ahi, const __nv_bfloat16* __restrict__ Alo,
    const __nv_bfloat16* __restrict__ Bhi, const __nv_bfloat16* __restrict__ Blo,
    float* __restrict__ C, int M, int N, int K)
{
    extern __shared__ char smraw[];
    uint32_t s0 = smem_u32(smraw);
    int tid = threadIdx.x, lane = tid & 31, wid = tid >> 5;
    int wm = wid & 1, wn = wid >> 1;
    int m0 = blockIdx.y * 128, n0 = blockIdx.x * 128;

    float acc[4][8][4];
    #pragma unroll
    for (int i = 0; i < 4; i++)
        #pragma unroll
        for (int j = 0; j < 8; j++)
            #pragma unroll
            for (int k = 0; k < 4; k++) acc[i][j][k] = 0.f;

    int nk = K >> 5;
    fill_stage(s0, 0, m0, n0, K, Ahi, Alo, Bhi, Blo, tid);
    asm volatile("cp.async.commit_group;" ::: "memory");
    fill_stage(s0 + STAGE_B, 1, m0, n0, K, Ahi, Alo, Bhi, Blo, tid);
    asm volatile("cp.async.commit_group;" ::: "memory");

    int a_row = wm * 64 + (lane & 15);
    int a_cb  = lane >> 4;
    int b_row = wn * 64 + (lane & 7) + (lane >> 4) * 8;
    int b_cb  = (lane >> 3) & 1;

    for (int kt = 0; kt < nk; kt++) {
        asm volatile("cp.async.wait_group 1;" ::: "memory");
        __syncthreads();

        if (kt + 2 < nk)
            fill_stage(s0 + ((kt + 2) % NST) * STAGE_B, kt + 2, m0, n0, K, Ahi, Alo, Bhi, Blo, tid);
        asm volatile("cp.async.commit_group;" ::: "memory");

        uint32_t sb = s0 + (kt % NST) * STAGE_B;

        // A frags (ks=0), double-buffered B frags, pipelined across 8 (ks,np) slots
        uint32_t a[2][4][4];       // [hi/lo][mtile][4]
        uint32_t bfr[2][2][4];     // [buf][hi/lo][4]
        #pragma unroll
        for (int hl = 0; hl < 2; hl++)
            #pragma unroll
            for (int mt = 0; mt < 4; mt++)
                ldm_x4(a[hl][mt], sb + hl * TILE_B + swz(a_row + mt * 16, a_cb));
        {
            uint32_t bo = swz(b_row, b_cb);
            ldm_x4(bfr[0][0], sb + 2 * TILE_B + bo);
            ldm_x4(bfr[0][1], sb + 3 * TILE_B + bo);
        }

        #pragma unroll
        for (int idx = 0; idx < 8; idx++) {
            int buf = idx & 1;
            if (idx < 7) {
                int nks = (idx + 1) >> 2, nnp = (idx + 1) & 3;
                uint32_t bo = swz(b_row + nnp * 16, nks * 2 + b_cb);
                ldm_x4(bfr[buf ^ 1][0], sb + 2 * TILE_B + bo);
                ldm_x4(bfr[buf ^ 1][1], sb + 3 * TILE_B + bo);
            }
            int np = idx & 3;
            uint32_t* bh = bfr[buf][0];
            uint32_t* bl = bfr[buf][1];
            #pragma unroll
            for (int mt = 0; mt < 4; mt++)
                #pragma unroll
                for (int nt = 0; nt < 2; nt++) {
                    float* d = acc[mt][np * 2 + nt];
                    mma_bf16(d, a[0][mt], &bh[nt * 2]);
                    mma_bf16(d, a[0][mt], &bl[nt * 2]);
                    mma_bf16(d, a[1][mt], &bh[nt * 2]);
                }
            if (idx == 3) {   // reload A for ks=1 after last ks=0 consumer
                #pragma unroll
                for (int hl = 0; hl < 2; hl++)
                    #pragma unroll
                    for (int mt = 0; mt < 4; mt++)
                        ldm_x4(a[hl][mt], sb + hl * TILE_B + swz(a_row + mt * 16, 2 + a_cb));
            }
        }
    }

    int row0 = m0 + wm * 64 + (lane >> 2);
    int col0 = n0 + wn * 64 + (lane & 3) * 2;
    #pragma unroll
    for (int mt = 0; mt < 4; mt++)
        #pragma unroll
        for (int nt = 0; nt < 8; nt++) {
            float* d = acc[mt][nt];
            long r = row0 + mt * 16;
            long c = col0 + nt * 8;
            *(float2*)(C + r * N + c)       = make_float2(d[0], d[1]);
            *(float2*)(C + (r + 8) * N + c) = make_float2(d[2], d[3]);
        }
}

// ---------------- RMSNorm + RoPE + scatter + fused hi/lo emission ----------------
__global__ void qkv_post_kernel(const float* __restrict__ rope,
                                const int*   __restrict__ start,
                                const float* __restrict__ qw,
                                const float* __restrict__ kw,
                                float* __restrict__ out_k,
                                float* __restrict__ out_v)
{
    int slot = blockIdx.x;
    int q    = blockIdx.y;
    int b    = blockIdx.z;
    int tid  = threadIdx.x;
    long row = ((long)b * QN + q) * NQKV;
    float x = g_qkv[row + (long)slot * DD + tid];
    int pos = start[b] + q;

    if (slot >= 40) {  // V: raw scatter + hi/lo
        int h = slot - 40;
        out_v[(((long)b * HKV + h) * MAXC + pos) * DD + tid] = x;
        long vi = (((long)b * HKV + h) * KLEN + pos) * DD + tid;
        __nv_bfloat16 vh = __float2bfloat16(x);
        gVc_hi[vi] = vh;
        gVc_lo[vi] = __float2bfloat16(x - __bfloat162float(vh));
        return;
    }

    __shared__ float red[4];
    __shared__ float sm[DD];
    float v2 = x * x;
    #pragma unroll
    for (int m = 16; m; m >>= 1) v2 += __shfl_xor_sync(0xffffffffu, v2, m);
    if ((tid & 31) == 0) red[tid >> 5] = v2;
    __syncthreads();
    float tot = red[0] + red[1] + red[2] + red[3];
    float scl = rsqrtf(tot * (1.f / DD) + 1e-6f);
    const float* w = (slot < 32) ? qw : kw;
    sm[tid] = x * scl * w[tid];
    __syncthreads();

    int i = (tid < 64) ? tid : tid - 64;
    float c = rope[(long)pos * DD + i];
    float s = rope[(long)pos * DD + 64 + i];
    float x1 = sm[i], x2 = sm[i + 64];
    float o = (tid < 64) ? (x1 * c - x2 * s) : (x2 * c + x1 * s);

    if (slot < 32) {   // Q: scaled hi/lo (log2 domain: fold log2(e))
        float xs = o * (SCALE * LOG2E);
        long qi = (((long)b * HH + slot) * QN + q) * DD + tid;
        __nv_bfloat16 qh = __float2bfloat16(xs);
        gQ_hi[qi] = qh;
        gQ_lo[qi] = __float2bfloat16(xs - __bfloat162float(qh));
    } else {           // K: fp32 scatter + hi/lo
        int h = slot - 32;
        out_k[(((long)b * HKV + h) * MAXC + pos) * DD + tid] = o;
        long ki = (((long)b * HKV + h) * KLEN + pos) * DD + tid;
        __nv_bfloat16 kh = __float2bfloat16(o);
        gKc_hi[ki] = kh;
        gKc_lo[ki] = __float2bfloat16(o - __bfloat162float(kh));
    }
}

// ================= tensor-core flash attention (bf16 hi/lo, log2-domain softmax) =================
#define APITCHB 272
#define AQ 64
#define ATILE (AQ * APITCHB)               // 17408 per hi or lo
#define ATTN_SMEM (6 * ATILE)              // 104448

__device__ __forceinline__ void load_tile64(uint32_t dst,
    const __nv_bfloat16* hi, const __nv_bfloat16* lo, long rowbase, int tid)
{
    #pragma unroll
    for (int i = 0; i < 8; i++) {
        int idx = tid + i * 128;
        int row = idx >> 4, ch = idx & 15;
        uint32_t d = dst + row * APITCHB + ch * 16;
        const long off = rowbase + (long)row * DD + (ch << 3);
        cp16(d, hi + off);
        cp16(d + ATILE, lo + off);
    }
}

__global__ void __launch_bounds__(128, 2) attn_mma()
{
    extern __shared__ char smraw[];
    uint32_t sQ = smem_u32(smraw);
    uint32_t sK = sQ + 2 * ATILE;
    uint32_t sV = sK + 2 * ATILE;
    int tid = threadIdx.x, lane = tid & 31, w = tid >> 5;
    int qt = gridDim.x - 1 - blockIdx.x;   // LPT: longest (largest qt) first
    int h = blockIdx.y, b = blockIdx.z;
    int kvh = h >> 2;
    int q0 = qt * 64;

    long qbase  = ((long)(b * HH + h) * QN + q0) * DD;
    long kvbase = (long)(b * HKV + kvh) * KLEN * DD;

    load_tile64(sQ, gQ_hi, gQ_lo, qbase, tid);
    load_tile64(sK, gKc_hi, gKc_lo, kvbase, tid);
    asm volatile("cp.async.commit_group;" ::: "memory");

    const int nc = 17 + qt;

    float O[16][4];
    #pragma unroll
    for (int i = 0; i < 16; i++)
        #pragma unroll
        for (int j = 0; j < 4; j++) O[i][j] = 0.f;
    float m0 = -1e30f, m1 = -1e30f, l0 = 0.f, l1 = 0.f;

    const int a_row  = w * 16 + (lane & 15);
    const int a_kb   = (lane >> 4) * 16;
    const int b_row  = (lane & 7) + (lane >> 4) * 8;
    const int b_kb   = ((lane >> 3) & 1) * 16;
    const int v_row  = lane & 15;
    const int v_col  = (lane >> 4) * 8;

    for (int c = 0; c < nc; c++) {
        int kb = c * 64;
        asm volatile("cp.async.wait_group 0;" ::: "memory");
        __syncthreads();

        load_tile64(sV, gVc_hi, gVc_lo, kvbase + (long)kb * DD, tid);
        asm volatile("cp.async.commit_group;" ::: "memory");

        // ---- S = Q K^T (log2-domain scores) ----
        float S[8][4];
        #pragma unroll
        for (int j = 0; j < 8; j++)
            #pragma unroll
            for (int k = 0; k < 4; k++) S[j][k] = 0.f;

        #pragma unroll
        for (int ks = 0; ks < 8; ks++) {
            uint32_t ah[4], al[4];
            uint32_t qa = sQ + a_row * APITCHB + ks * 32 + a_kb;
            ldm_x4(ah, qa);
            ldm_x4(al, qa + ATILE);
            #pragma unroll
            for (int np = 0; np < 4; np++) {
                uint32_t bh[4], bl[4];
                uint32_t ka = sK + (np * 16 + b_row) * APITCHB + ks * 32 + b_kb;
                ldm_x4(bh, ka);
                ldm_x4(bl, ka + ATILE);
                #pragma unroll
                for (int nt = 0; nt < 2; nt++) {
                    float* d = S[np * 2 + nt];
                    mma_bf16(d, ah, &bh[nt * 2]);
                    mma_bf16(d, ah, &bl[nt * 2]);
                    mma_bf16(d, al, &bh[nt * 2]);
                }
            }
        }

        if (c == nc - 1) {
            int klim0 = PAST + q0 + w * 16 + (lane >> 2);
            int klim1 = klim0 + 8;
            #pragma unroll
            for (int j = 0; j < 8; j++) {
                int col = kb + j * 8 + (lane & 3) * 2;
                if (col > klim0)     S[j][0] = -1e30f;
                if (col + 1 > klim0) S[j][1] = -1e30f;
                if (col > klim1)     S[j][2] = -1e30f;
                if (col + 1 > klim1) S[j][3] = -1e30f;
            }
        }

        // ---- online softmax (base-2) ----
        float mx0 = -1e30f, mx1 = -1e30f;
        #pragma unroll
        for (int j = 0; j < 8; j++) {
            mx0 = fmaxf(mx0, fmaxf(S[j][0], S[j][1]));
            mx1 = fmaxf(mx1, fmaxf(S[j][2], S[j][3]));
        }
        mx0 = fmaxf(mx0, __shfl_xor_sync(0xffffffffu, mx0, 1));
        mx0 = fmaxf(mx0, __shfl_xor_sync(0xffffffffu, mx0, 2));
        mx1 = fmaxf(mx1, __shfl_xor_sync(0xffffffffu, mx1, 1));
        mx1 = fmaxf(mx1, __shfl_xor_sync(0xffffffffu, mx1, 2));
        float mn0 = fmaxf(m0, mx0), mn1 = fmaxf(m1, mx1);
        float al0 = ex2(m0 - mn0), al1 = ex2(m1 - mn1);
        float r0 = 0.f, r1 = 0.f;
        #pragma unroll
        for (int j = 0; j < 8; j++) {
            S[j][0] = ex2(S[j][0] - mn0);
            S[j][1] = ex2(S[j][1] - mn0);
            S[j][2] = ex2(S[j][2] - mn1);
            S[j][3] = ex2(S[j][3] - mn1);
            r0 += S[j][0] + S[j][1];
            r1 += S[j][2] + S[j][3];
        }
        r0 += __shfl_xor_sync(0xffffffffu, r0, 1);
        r0 += __shfl_xor_sync(0xffffffffu, r0, 2);
        r1 += __shfl_xor_sync(0xffffffffu, r1, 1);
        r1 += __shfl_xor_sync(0xffffffffu, r1, 2);
        l0 = l0 * al0 + r0;
        l1 = l1 * al1 + r1;
        m0 = mn0; m1 = mn1;
        #pragma unroll
        for (int i = 0; i < 16; i++) {
            O[i][0] *= al0; O[i][1] *= al0;
            O[i][2] *= al1; O[i][3] *= al1;
        }

        // ---- P -> bf16 hi/lo A-frags ----
        uint32_t pa_h[4][4], pa_l[4][4];
        #pragma unroll
        for (int kt = 0; kt < 4; kt++) {
            int j0 = 2 * kt, j1 = 2 * kt + 1;
            float v00 = S[j0][0], v01 = S[j0][1], v02 = S[j0][2], v03 = S[j0][3];
            float v10 = S[j1][0], v11 = S[j1][1], v12 = S[j1][2], v13 = S[j1][3];
            pa_h[kt][0] = pack_bf2(v00, v01);
            pa_h[kt][1] = pack_bf2(v02, v03);
            pa_h[kt][2] = pack_bf2(v10, v11);
            pa_h[kt][3] = pack_bf2(v12, v13);
            __nv_bfloat162* hp;
            hp = (__nv_bfloat162*)&pa_h[kt][0];
            pa_l[kt][0] = pack_bf2(v00 - __bfloat162float(hp->x), v01 - __bfloat162float(hp->y));
            hp = (__nv_bfloat162*)&pa_h[kt][1];
            pa_l[kt][1] = pack_bf2(v02 - __bfloat162float(hp->x), v03 - __bfloat162float(hp->y));
            hp = (__nv_bfloat162*)&pa_h[kt][2];
            pa_l[kt][2] = pack_bf2(v10 - __bfloat162float(hp->x), v11 - __bfloat162float(hp->y));
            hp = (__nv_bfloat162*)&pa_h[kt][3];
            pa_l[kt][3] = pack_bf2(v12 - __bfloat162float(hp->x), v13 - __bfloat162float(hp->y));
        }

        __syncthreads();
        if (c + 1 < nc) {
            load_tile64(sK, gKc_hi, gKc_lo, kvbase + (long)(kb + 64) * DD, tid);
            asm volatile("cp.async.commit_group;" ::: "memory");
            asm volatile("cp.async.wait_group 1;" ::: "memory");
        } else {
            asm volatile("cp.async.wait_group 0;" ::: "memory");
        }
        __syncthreads();

        // ---- O += P V ----
        #pragma unroll
        for (int kt = 0; kt < 4; kt++) {
            #pragma unroll
            for (int np = 0; np < 8; np++) {
                uint32_t vh[4], vl[4];
                uint32_t va = sV + (kt * 16 + v_row) * APITCHB + (np * 16 + v_col) * 2;
                ldm_x4t(vh, va);
                ldm_x4t(vl, va + ATILE);
                #pragma unroll
                for (int nt = 0; nt < 2; nt++) {
                    float* d = O[np * 2 + nt];
                    mma_bf16(d, pa_h[kt], &vh[nt * 2]);
                    mma_bf16(d, pa_h[kt], &vl[nt * 2]);
                    mma_bf16(d, pa_l[kt], &vh[nt * 2]);
                }
            }
        }
        __syncthreads();
    }

    float inv0 = 1.f / l0, inv1 = 1.f / l1;
    int row0 = q0 + w * 16 + (lane >> 2);
    float* ob = g_attnO + ((long)(b * HH + h) * QN) * DD;
    #pragma unroll
    for (int np = 0; np < 16; np++) {
        int col = np * 8 + (lane & 3) * 2;
        *(float2*)(ob + (long)row0 * DD + col)       = make_float2(O[np][0] * inv0, O[np][1] * inv0);
        *(float2*)(ob + (long)(row0 + 8) * DD + col) = make_float2(O[np][2] * inv1, O[np][3] * inv1);
    }
}

// ---------------- group sum + hi/lo conversion ----------------
__global__ void group_sum_kernel()
{
    long i = (long)blockIdx.x * 256 + threadIdx.x;
    if (i >= (long)BB * QN * HKV * DD) return;
    int d = (int)(i & (DD - 1));
    long t = i >> 7;
    int kvh = (int)(t & (HKV - 1));
    t >>= 3;
    int q = (int)(t % QN);
    int b = (int)(t / QN);
    float sum = 0.f;
    #pragma unroll
    for (int g = 0; g < GROUPS; g++)
        sum += g_attnO[(((long)b * HH + kvh * GROUPS + g) * QN + q) * DD + d];
    __nv_bfloat16 h = __float2bfloat16(sum);
    gXo_hi[i] = h;
    gXo_lo[i] = __float2bfloat16(sum - __bfloat162float(h));
}

// ---------------- launch ----------------
static __nv_bfloat16* sym_addr_b(const void* sym) {
    void* p = nullptr;
    cudaGetSymbolAddress(&p, sym);
    return (__nv_bfloat16*)p;
}
static float* sym_addr_f(const void* sym) {
    void* p = nullptr;
    cudaGetSymbolAddress(&p, sym);
    return (float*)p;
}

extern "C" void kernel_launch(void* const* d_in, const int* in_sizes, int n_in,
                              void* d_out, int out_size)
{
    const float* hidden = (const float*)d_in[0];
    const float* kcache = (const float*)d_in[1];
    const float* vcache = (const float*)d_in[2];
    const float* rope   = (const float*)d_in[3];
    const int*   start  = (const int*)  d_in[5];
    const float* w_qkv  = (const float*)d_in[6];
    const float* w_o    = (const float*)d_in[7];
    const float* qw     = (const float*)d_in[8];
    const float* kw     = (const float*)d_in[9];

    float* out      = (float*)d_out;
    float* out_attn = out;
    float* out_k    = out + OUT_SZ1;
    float* out_v    = out + OUT_SZ1 + CACHE_SZ;

    float* s_qkv = sym_addr_f(g_qkv);
    __nv_bfloat16* sA_hi = sym_addr_b(gA_hi);  __nv_bfloat16* sA_lo = sym_addr_b(gA_lo);
    __nv_bfloat16* sWq_hi = sym_addr_b(gWq_hi); __nv_bfloat16* sWq_lo = sym_addr_b(gWq_lo);
    __nv_bfloat16* sWo_hi = sym_addr_b(gWo_hi); __nv_bfloat16* sWo_lo = sym_addr_b(gWo_lo);
    __nv_bfloat16* sXo_hi = sym_addr_b(gXo_hi); __nv_bfloat16* sXo_lo = sym_addr_b(gXo_lo);

    cudaFuncSetAttribute(gemm_mma, cudaFuncAttributeMaxDynamicSharedMemorySize, GEMM_SMEM);
    cudaFuncSetAttribute(attn_mma, cudaFuncAttributeMaxDynamicSharedMemorySize, ATTN_SMEM);

    // 1. present caches
    cudaMemcpyAsync(out_k, kcache, (size_t)CACHE_SZ * sizeof(float), cudaMemcpyDeviceToDevice, 0);
    cudaMemcpyAsync(out_v, vcache, (size_t)CACHE_SZ * sizeof(float), cudaMemcpyDeviceToDevice, 0);

    // 2. hi/lo conversions (A, weights, PAST region of caches)
    conv_hilo<<<(BB*QN*HID + 255) / 256, 256>>>(hidden, sA_hi, sA_lo, BB*QN*HID);
    conv_hilo_T<<<dim3(NQKV / 32, HID / 32), dim3(32, 8)>>>(w_qkv, sWq_hi, sWq_lo, HID, NQKV);
    conv_hilo_T<<<dim3(HID / 32, (HKV*DD) / 32), dim3(32, 8)>>>(w_o, sWo_hi, sWo_lo, HKV*DD, HID);
    kv_hilo_past<<<(BB*HKV*PAST*DD + 255) / 256, 256>>>(kcache, vcache);

    // 3. QKV projection
    gemm_mma<<<dim3(NQKV / 128, (BB*QN) / 128), 128, GEMM_SMEM>>>(
        sA_hi, sA_lo, sWq_hi, sWq_lo, s_qkv, BB*QN, NQKV, HID);

    // 4. RMSNorm + RoPE + scatter + fused Q/K/V hi/lo
    qkv_post_kernel<<<dim3(48, QN, BB), 128>>>(rope, start, qw, kw, out_k, out_v);

    // 5. tensor-core flash attention (LPT order, log2 softmax)
    attn_mma<<<dim3(QN / 64, HH, BB), 128, ATTN_SMEM>>>();

    // 6. group-sum + hi/lo
    group_sum_kernel<<<(BB*QN*HKV*DD + 255) / 256, 256>>>();

    // 7. output projection
    gemm_mma<<<dim3(HID / 128, (BB*QN) / 128), 128, GEMM_SMEM>>>(
        sXo_hi, sXo_lo, sWo_hi, sWo_lo, out_attn, BB*QN, HID, HKV*DD);
}

// round 11
// speedup vs baseline: 1.4523x; 1.3548x over previous
#include <cuda_runtime.h>
#include <cuda_fp16.h>
#include <cstdint>

// ---------------- problem constants ----------------
#define BB    2
#define QN    1024
#define PAST  1024
#define MAXC  4096
#define HH    32
#define HKV   8
#define DD    128
#define HID   4096
#define KLEN  (PAST + QN)          // 2048
#define NQKV  ((HH + 2*HKV) * DD)  // 6144
#define GROUPS (HH / HKV)
#define SCALE 0.08838834764831845f
#define LOG2E 1.4426950408889634f

#define OUT_SZ1 (BB*QN*HID)
#define CACHE_SZ (BB*HKV*MAXC*DD)

// ---------------- scratch (device globals) ----------------
__device__ __align__(16) float g_qkv  [BB*QN*NQKV];
__device__ __align__(16) float g_attnO[BB*HH*QN*DD];

__device__ __align__(16) __half gA_hi [BB*QN*HID];
__device__ __align__(16) __half gA_lo [BB*QN*HID];
__device__ __align__(16) __half gWq_h [NQKV*HID];     // transposed [N][K], hi only
__device__ __align__(16) __half gWo_h [HID*HKV*DD];   // transposed, hi only
__device__ __align__(16) __half gXo_hi[BB*QN*HKV*DD];
__device__ __align__(16) __half gXo_lo[BB*QN*HKV*DD];

// attention fp16 operands (Q pre-scaled by SCALE*LOG2E, hi/lo; K,V single fp16)
__device__ __align__(16) __half gQ_hi [BB*HH*QN*DD];
__device__ __align__(16) __half gQ_lo [BB*HH*QN*DD];
__device__ __align__(16) __half gKc_h [BB*HKV*KLEN*DD];
__device__ __align__(16) __half gVc_h [BB*HKV*KLEN*DD];

// ================= PTX helpers (sm_80+ portable subset) =================
__device__ __forceinline__ uint32_t smem_u32(const void* p) {
    uint32_t a;
    asm("{ .reg .u64 t; cvta.to.shared.u64 t, %1; cvt.u32.u64 %0, t; }" : "=r"(a) : "l"(p));
    return a;
}
__device__ __forceinline__ void ldm_x4(uint32_t* r, uint32_t addr) {
    asm volatile("ldmatrix.sync.aligned.m8n8.x4.shared.b16 {%0,%1,%2,%3}, [%4];"
                 : "=r"(r[0]), "=r"(r[1]), "=r"(r[2]), "=r"(r[3]) : "r"(addr));
}
__device__ __forceinline__ void ldm_x4t(uint32_t* r, uint32_t addr) {
    asm volatile("ldmatrix.sync.aligned.m8n8.x4.trans.shared.b16 {%0,%1,%2,%3}, [%4];"
                 : "=r"(r[0]), "=r"(r[1]), "=r"(r[2]), "=r"(r[3]) : "r"(addr));
}
__device__ __forceinline__ void mma_f16(float* d, const uint32_t* a, const uint32_t* b) {
    asm volatile(
        "mma.sync.aligned.m16n8k16.row.col.f32.f16.f16.f32 "
        "{%0,%1,%2,%3}, {%4,%5,%6,%7}, {%8,%9}, {%0,%1,%2,%3};"
        : "+f"(d[0]), "+f"(d[1]), "+f"(d[2]), "+f"(d[3])
        : "r"(a[0]), "r"(a[1]), "r"(a[2]), "r"(a[3]), "r"(b[0]), "r"(b[1]));
}
__device__ __forceinline__ void cp16(uint32_t dst, const void* src) {
    asm volatile("cp.async.cg.shared.global [%0], [%1], 16;" :: "r"(dst), "l"(src));
}
__device__ __forceinline__ uint32_t pack_h2(float x, float y) {
    __half2 h = __floats2half2_rn(x, y);
    return *(uint32_t*)&h;
}
__device__ __forceinline__ float ex2(float x) {
    float y;
    asm("ex2.approx.f32 %0, %1;" : "=f"(y) : "f"(x));
    return y;
}

// ================= conversion kernels =================
// A (hidden) -> fp16 hi/lo
__global__ void conv_hilo(const float* __restrict__ src,
                          __half* __restrict__ hi, __half* __restrict__ lo, int n) {
    int i = blockIdx.x * 256 + threadIdx.x;
    if (i >= n) return;
    float x = src[i];
    __half h = __float2half_rn(x);
    hi[i] = h;
    lo[i] = __float2half_rn(x - __half2float(h));
}

// src [K][N] fp32 -> hi-only [N][K] fp16 (transposed)
__global__ void conv_T_h(const float* __restrict__ src, __half* __restrict__ hi,
                         int K, int N) {
    __shared__ float t[32][33];
    int bn = blockIdx.x * 32, bk = blockIdx.y * 32;
    int x = threadIdx.x, y = threadIdx.y;
    #pragma unroll
    for (int i = 0; i < 32; i += 8)
        t[y + i][x] = src[(long)(bk + y + i) * N + bn + x];
    __syncthreads();
    #pragma unroll
    for (int i = 0; i < 32; i += 8)
        hi[(long)(bn + y + i) * K + bk + x] = __float2half_rn(t[x][y + i]);
}

// PAST rows of the caches -> fp16
__global__ void kv_h_past(const float* __restrict__ kc, const float* __restrict__ vc) {
    long i = (long)blockIdx.x * 256 + threadIdx.x;
    if (i >= (long)BB * HKV * PAST * DD) return;
    int d = (int)(i & (DD - 1));
    long t = i >> 7;
    int pos = (int)(t & (PAST - 1));
    t >>= 10;                               // t = b*HKV + h
    long src = (t * MAXC + pos) * DD + d;
    long dst = (t * KLEN + pos) * DD + d;
    gKc_h[dst] = __float2half_rn(kc[src]);
    gVc_h[dst] = __float2half_rn(vc[src]);
}

// ================= warp-MMA fp16 2-term GEMM (3-stage, swizzled, 64x64 warp tile) =================
// C = (Ah+Al) @ Bh^T.  Tiles: Ah, Al, Bh (128 rows x 64B per K32 chunk).
#define TILE_B  8192
#define STAGE_B (3 * TILE_B)              // 24576
#define NST     3
#define GEMM_SMEM (NST * STAGE_B)         // 73728

__device__ __forceinline__ uint32_t swz(int row, int ch) {
    return (uint32_t)(row * 64 + ((ch ^ ((row >> 1) & 3)) << 4));
}

__device__ __forceinline__ void fill_stage(
    uint32_t sb, int kt, int m0, int n0, int K,
    const __half* Ahi, const __half* Alo, const __half* Bh, int tid)
{
    long k0 = (long)kt * 32;
    const __half* bases[3] = {Ahi, Alo, Bh};
    #pragma unroll
    for (int t = 0; t < 3; t++) {
        const __half* bp = bases[t];
        int r0 = (t < 2) ? m0 : n0;
        #pragma unroll
        for (int i = 0; i < 4; i++) {
            int idx = tid + i * 128;
            int row = idx >> 2, ch = idx & 3;
            cp16(sb + t * TILE_B + swz(row, ch), bp + (long)(r0 + row) * K + k0 + ch * 8);
        }
    }
}

__global__ void __launch_bounds__(128, 2) gemm_mma(
    const __half* __restrict__ Ahi, const __half* __restrict__ Alo,
    const __half* __restrict__ Bh,
    float* __restrict__ C, int M, int N, int K)
{
    extern __shared__ char smraw[];
    uint32_t s0 = smem_u32(smraw);
    int tid = threadIdx.x, lane = tid & 31, wid = tid >> 5;
    int wm = wid & 1, wn = wid >> 1;
    int m0 = blockIdx.y * 128, n0 = blockIdx.x * 128;

    float acc[4][8][4];
    #pragma unroll
    for (int i = 0; i < 4; i++)
        #pragma unroll
        for (int j = 0; j < 8; j++)
            #pragma unroll
            for (int k = 0; k < 4; k++) acc[i][j][k] = 0.f;

    int nk = K >> 5;
    fill_stage(s0, 0, m0, n0, K, Ahi, Alo, Bh, tid);
    asm volatile("cp.async.commit_group;" ::: "memory");
    fill_stage(s0 + STAGE_B, 1, m0, n0, K, Ahi, Alo, Bh, tid);
    asm volatile("cp.async.commit_group;" ::: "memory");

    int a_row = wm * 64 + (lane & 15);
    int a_cb  = lane >> 4;
    int b_row = wn * 64 + (lane & 7) + (lane >> 4) * 8;
    int b_cb  = (lane >> 3) & 1;

    for (int kt = 0; kt < nk; kt++) {
        asm volatile("cp.async.wait_group 1;" ::: "memory");
        __syncthreads();

        if (kt + 2 < nk)
            fill_stage(s0 + ((kt + 2) % NST) * STAGE_B, kt + 2, m0, n0, K, Ahi, Alo, Bh, tid);
        asm volatile("cp.async.commit_group;" ::: "memory");

        uint32_t sb = s0 + (kt % NST) * STAGE_B;
        uint32_t sbB = sb + 2 * TILE_B;

        uint32_t a[2][4][4];       // [hi/lo][mtile][4]
        uint32_t bfr[2][4];        // double-buffered B frags
        #pragma unroll
        for (int hl = 0; hl < 2; hl++)
            #pragma unroll
            for (int mt = 0; mt < 4; mt++)
                ldm_x4(a[hl][mt], sb + hl * TILE_B + swz(a_row + mt * 16, a_cb));
        ldm_x4(bfr[0], sbB + swz(b_row, b_cb));

        #pragma unroll
        for (int idx = 0; idx < 8; idx++) {
            int buf = idx & 1;
            if (idx < 7) {
                int nks = (idx + 1) >> 2, nnp = (idx + 1) & 3;
                ldm_x4(bfr[buf ^ 1], sbB + swz(b_row + nnp * 16, nks * 2 + b_cb));
            }
            int np = idx & 3;
            uint32_t* bh = bfr[buf];
            #pragma unroll
            for (int mt = 0; mt < 4; mt++)
                #pragma unroll
                for (int nt = 0; nt < 2; nt++) {
                    float* d = acc[mt][np * 2 + nt];
                    mma_f16(d, a[0][mt], &bh[nt * 2]);
                    mma_f16(d, a[1][mt], &bh[nt * 2]);
                }
            if (idx == 3) {
                #pragma unroll
                for (int hl = 0; hl < 2; hl++)
                    #pragma unroll
                    for (int mt = 0; mt < 4; mt++)
                        ldm_x4(a[hl][mt], sb + hl * TILE_B + swz(a_row + mt * 16, 2 + a_cb));
            }
        }
    }

    int row0 = m0 + wm * 64 + (lane >> 2);
    int col0 = n0 + wn * 64 + (lane & 3) * 2;
    #pragma unroll
    for (int mt = 0; mt < 4; mt++)
        #pragma unroll
        for (int nt = 0; nt < 8; nt++) {
            float* d = acc[mt][nt];
            long r = row0 + mt * 16;
            long c = col0 + nt * 8;
            *(float2*)(C + r * N + c)       = make_float2(d[0], d[1]);
            *(float2*)(C + (r + 8) * N + c) = make_float2(d[2], d[3]);
        }
}

// ---------------- RMSNorm + RoPE + scatter + fused fp16 emission ----------------
__global__ void qkv_post_kernel(const float* __restrict__ rope,
                                const int*   __restrict__ start,
                                const float* __restrict__ qw,
                                const float* __restrict__ kw,
                                float* __restrict__ out_k,
                                float* __restrict__ out_v)
{
    int slot = blockIdx.x;
    int q    = blockIdx.y;
    int b    = blockIdx.z;
    int tid  = threadIdx.x;
    long row = ((long)b * QN + q) * NQKV;
    float x = g_qkv[row + (long)slot * DD + tid];
    int pos = start[b] + q;

    if (slot >= 40) {  // V
        int h = slot - 40;
        out_v[(((long)b * HKV + h) * MAXC + pos) * DD + tid] = x;
        gVc_h[(((long)b * HKV + h) * KLEN + pos) * DD + tid] = __float2half_rn(x);
        return;
    }

    __shared__ float red[4];
    __shared__ float sm[DD];
    float v2 = x * x;
    #pragma unroll
    for (int m = 16; m; m >>= 1) v2 += __shfl_xor_sync(0xffffffffu, v2, m);
    if ((tid & 31) == 0) red[tid >> 5] = v2;
    __syncthreads();
    float tot = red[0] + red[1] + red[2] + red[3];
    float scl = rsqrtf(tot * (1.f / DD) + 1e-6f);
    const float* w = (slot < 32) ? qw : kw;
    sm[tid] = x * scl * w[tid];
    __syncthreads();

    int i = (tid < 64) ? tid : tid - 64;
    float c = rope[(long)pos * DD + i];
    float s = rope[(long)pos * DD + 64 + i];
    float x1 = sm[i], x2 = sm[i + 64];
    float o = (tid < 64) ? (x1 * c - x2 * s) : (x2 * c + x1 * s);

    if (slot < 32) {   // Q: scaled fp16 hi/lo (log2 domain)
        float xs = o * (SCALE * LOG2E);
        long qi = (((long)b * HH + slot) * QN + q) * DD + tid;
        __half qh = __float2half_rn(xs);
        gQ_hi[qi] = qh;
        gQ_lo[qi] = __float2half_rn(xs - __half2float(qh));
    } else {           // K
        int h = slot - 32;
        out_k[(((long)b * HKV + h) * MAXC + pos) * DD + tid] = o;
        gKc_h[(((long)b * HKV + h) * KLEN + pos) * DD + tid] = __float2half_rn(o);
    }
}

// ================= flash attention (fp16, Q hi/lo + P hi/lo; K/V single, double-buffered) =================
#define APITCHB 272
#define AQ 64
#define ATILE (AQ * APITCHB)               // 17408
#define ATTN_SMEM (6 * ATILE)              // Qh,Ql,K0,K1,V0,V1 = 104448

__device__ __forceinline__ void load_tile_h(uint32_t dst,
    const __half* src, long rowbase, int tid)
{
    #pragma unroll
    for (int i = 0; i < 8; i++) {
        int idx = tid + i * 128;
        int row = idx >> 4, ch = idx & 15;
        cp16(dst + row * APITCHB + ch * 16, src + rowbase + (long)row * DD + (ch << 3));
    }
}

__global__ void __launch_bounds__(128, 2) attn_mma()
{
    extern __shared__ char smraw[];
    uint32_t sQh = smem_u32(smraw);
    uint32_t sQl = sQh + ATILE;
    uint32_t sK0 = sQh + 2 * ATILE;        // K buffers at +2,+3; V at +4,+5
    uint32_t sV0 = sQh + 4 * ATILE;
    int tid = threadIdx.x, lane = tid & 31, w = tid >> 5;
    int qt = gridDim.x - 1 - blockIdx.x;   // LPT
    int h = blockIdx.y, b = blockIdx.z;
    int kvh = h >> 2;
    int q0 = qt * 64;

    long qbase  = ((long)(b * HH + h) * QN + q0) * DD;
    long kvbase = (long)(b * HKV + kvh) * KLEN * DD;

    // group 0: Q hi/lo + K0 + V0 ; group 1: K1 + V1
    load_tile_h(sQh, gQ_hi, qbase, tid);
    load_tile_h(sQl, gQ_lo, qbase, tid);
    load_tile_h(sK0, gKc_h, kvbase, tid);
    load_tile_h(sV0, gVc_h, kvbase, tid);
    asm volatile("cp.async.commit_group;" ::: "memory");
    load_tile_h(sK0 + ATILE, gKc_h, kvbase + 64 * DD, tid);
    load_tile_h(sV0 + ATILE, gVc_h, kvbase + 64 * DD, tid);
    asm volatile("cp.async.commit_group;" ::: "memory");

    const int nc = 17 + qt;

    float O[16][4];
    #pragma unroll
    for (int i = 0; i < 16; i++)
        #pragma unroll
        for (int j = 0; j < 4; j++) O[i][j] = 0.f;
    float m0 = -1e30f, m1 = -1e30f, l0 = 0.f, l1 = 0.f;

    const int a_row  = w * 16 + (lane & 15);
    const int a_kb   = (lane >> 4) * 16;
    const int b_row  = (lane & 7) + (lane >> 4) * 8;
    const int b_kb   = ((lane >> 3) & 1) * 16;
    const int v_row  = lane & 15;
    const int v_col  = (lane >> 4) * 8;

    for (int c = 0; c < nc; c++) {
        int buf = c & 1;
        uint32_t sK = sK0 + buf * ATILE;
        uint32_t sV = sV0 + buf * ATILE;

        asm volatile("cp.async.wait_group 1;" ::: "memory");
        __syncthreads();

        // ---- S = Q K^T (2-term) ----
        float S[8][4];
        #pragma unroll
        for (int j = 0; j < 8; j++)
            #pragma unroll
            for (int k = 0; k < 4; k++) S[j][k] = 0.f;

        #pragma unroll
        for (int ks = 0; ks < 8; ks++) {
            uint32_t qh[4], ql[4];
            uint32_t qa = sQh + a_row * APITCHB + ks * 32 + a_kb;
            ldm_x4(qh, qa);
            ldm_x4(ql, qa + ATILE);
            #pragma unroll
            for (int np = 0; np < 4; np++) {
                uint32_t kf[4];
                ldm_x4(kf, sK + (np * 16 + b_row) * APITCHB + ks * 32 + b_kb);
                #pragma unroll
                for (int nt = 0; nt < 2; nt++) {
                    float* d = S[np * 2 + nt];
                    mma_f16(d, qh, &kf[nt * 2]);
                    mma_f16(d, ql, &kf[nt * 2]);
                }
            }
        }

        if (c == nc - 1) {
            int klim0 = PAST + q0 + w * 16 + (lane >> 2);
            int klim1 = klim0 + 8;
            int kb = c * 64;
            #pragma unroll
            for (int j = 0; j < 8; j++) {
                int col = kb + j * 8 + (lane & 3) * 2;
                if (col > klim0)     S[j][0] = -1e30f;
                if (col + 1 > klim0) S[j][1] = -1e30f;
                if (col > klim1)     S[j][2] = -1e30f;
                if (col + 1 > klim1) S[j][3] = -1e30f;
            }
        }

        // ---- online softmax (base-2) ----
        float mx0 = -1e30f, mx1 = -1e30f;
        #pragma unroll
        for (int j = 0; j < 8; j++) {
            mx0 = fmaxf(mx0, fmaxf(S[j][0], S[j][1]));
            mx1 = fmaxf(mx1, fmaxf(S[j][2], S[j][3]));
        }
        mx0 = fmaxf(mx0, __shfl_xor_sync(0xffffffffu, mx0, 1));
        mx0 = fmaxf(mx0, __shfl_xor_sync(0xffffffffu, mx0, 2));
        mx1 = fmaxf(mx1, __shfl_xor_sync(0xffffffffu, mx1, 1));
        mx1 = fmaxf(mx1, __shfl_xor_sync(0xffffffffu, mx1, 2));
        float mn0 = fmaxf(m0, mx0), mn1 = fmaxf(m1, mx1);
        float al0 = ex2(m0 - mn0), al1 = ex2(m1 - mn1);
        float r0 = 0.f, r1 = 0.f;
        #pragma unroll
        for (int j = 0; j < 8; j++) {
            S[j][0] = ex2(S[j][0] - mn0);
            S[j][1] = ex2(S[j][1] - mn0);
            S[j][2] = ex2(S[j][2] - mn1);
            S[j][3] = ex2(S[j][3] - mn1);
            r0 += S[j][0] + S[j][1];
            r1 += S[j][2] + S[j][3];
        }
        r0 += __shfl_xor_sync(0xffffffffu, r0, 1);
        r0 += __shfl_xor_sync(0xffffffffu, r0, 2);
        r1 += __shfl_xor_sync(0xffffffffu, r1, 1);
        r1 += __shfl_xor_sync(0xffffffffu, r1, 2);
        l0 = l0 * al0 + r0;
        l1 = l1 * al1 + r1;
        m0 = mn0; m1 = mn1;
        #pragma unroll
        for (int i = 0; i < 16; i++) {
            O[i][0] *= al0; O[i][1] *= al0;
            O[i][2] *= al1; O[i][3] *= al1;
        }

        // ---- P -> fp16 hi/lo A-frags ----
        uint32_t pa_h[4][4], pa_l[4][4];
        #pragma unroll
        for (int kt = 0; kt < 4; kt++) {
            int j0 = 2 * kt, j1 = 2 * kt + 1;
            float v00 = S[j0][0], v01 = S[j0][1], v02 = S[j0][2], v03 = S[j0][3];
            float v10 = S[j1][0], v11 = S[j1][1], v12 = S[j1][2], v13 = S[j1][3];
            pa_h[kt][0] = pack_h2(v00, v01);
            pa_h[kt][1] = pack_h2(v02, v03);
            pa_h[kt][2] = pack_h2(v10, v11);
            pa_h[kt][3] = pack_h2(v12, v13);
            __half2* hp;
            hp = (__half2*)&pa_h[kt][0];
            pa_l[kt][0] = pack_h2(v00 - __half2float(hp->x), v01 - __half2float(hp->y));
            hp = (__half2*)&pa_h[kt][1];
            pa_l[kt][1] = pack_h2(v02 - __half2float(hp->x), v03 - __half2float(hp->y));
            hp = (__half2*)&pa_h[kt][2];
            pa_l[kt][2] = pack_h2(v10 - __half2float(hp->x), v11 - __half2float(hp->y));
            hp = (__half2*)&pa_h[kt][3];
            pa_l[kt][3] = pack_h2(v12 - __half2float(hp->x), v13 - __half2float(hp->y));
        }

        // ---- O += P V (2-term) ----
        #pragma unroll
        for (int kt = 0; kt < 4; kt++) {
            #pragma unroll
            for (int np = 0; np < 8; np++) {
                uint32_t vf[4];
                ldm_x4t(vf, sV + (kt * 16 + v_row) * APITCHB + (np * 16 + v_col) * 2);
                #pragma unroll
                for (int nt = 0; nt < 2; nt++) {
                    float* d = O[np * 2 + nt];
                    mma_f16(d, pa_h[kt], &vf[nt * 2]);
                    mma_f16(d, pa_l[kt], &vf[nt * 2]);
                }
            }
        }
        __syncthreads();   // all warps done with K[buf]/V[buf] before refill

        if (c + 2 < nc) {
            long nb = kvbase + (long)(c + 2) * 64 * DD;
            load_tile_h(sK, gKc_h, nb, tid);
            load_tile_h(sV, gVc_h, nb, tid);
        }
        asm volatile("cp.async.commit_group;" ::: "memory");
    }

    float inv0 = 1.f / l0, inv1 = 1.f / l1;
    int row0 = q0 + w * 16 + (lane >> 2);
    float* ob = g_attnO + ((long)(b * HH + h) * QN) * DD;
    #pragma unroll
    for (int np = 0; np < 16; np++) {
        int col = np * 8 + (lane & 3) * 2;
        *(float2*)(ob + (long)row0 * DD + col)       = make_float2(O[np][0] * inv0, O[np][1] * inv0);
        *(float2*)(ob + (long)(row0 + 8) * DD + col) = make_float2(O[np][2] * inv1, O[np][3] * inv1);
    }
}

// ---------------- group sum + fp16 hi/lo conversion ----------------
__global__ void group_sum_kernel()
{
    long i = (long)blockIdx.x * 256 + threadIdx.x;
    if (i >= (long)BB * QN * HKV * DD) return;
    int d = (int)(i & (DD - 1));
    long t = i >> 7;
    int kvh = (int)(t & (HKV - 1));
    t >>= 3;
    int q = (int)(t % QN);
    int b = (int)(t / QN);
    float sum = 0.f;
    #pragma unroll
    for (int g = 0; g < GROUPS; g++)
        sum += g_attnO[(((long)b * HH + kvh * GROUPS + g) * QN + q) * DD + d];
    __half h = __float2half_rn(sum);
    gXo_hi[i] = h;
    gXo_lo[i] = __float2half_rn(sum - __half2float(h));
}

// ---------------- launch ----------------
static __half* sym_addr_h(const void* sym) {
    void* p = nullptr;
    cudaGetSymbolAddress(&p, sym);
    return (__half*)p;
}
static float* sym_addr_f(const void* sym) {
    void* p = nullptr;
    cudaGetSymbolAddress(&p, sym);
    return (float*)p;
}

extern "C" void kernel_launch(void* const* d_in, const int* in_sizes, int n_in,
                              void* d_out, int out_size)
{
    const float* hidden = (const float*)d_in[0];
    const float* kcache = (const float*)d_in[1];
    const float* vcache = (const float*)d_in[2];
    const float* rope   = (const float*)d_in[3];
    const int*   start  = (const int*)  d_in[5];
    const float* w_qkv  = (const float*)d_in[6];
    const float* w_o    = (const float*)d_in[7];
    const float* qw     = (const float*)d_in[8];
    const float* kw     = (const float*)d_in[9];

    float* out      = (float*)d_out;
    float* out_attn = out;
    float* out_k    = out + OUT_SZ1;
    float* out_v    = out + OUT_SZ1 + CACHE_SZ;

    float* s_qkv = sym_addr_f(g_qkv);
    __half* sA_hi = sym_addr_h(gA_hi);  __half* sA_lo = sym_addr_h(gA_lo);
    __half* sWq_h = sym_addr_h(gWq_h);  __half* sWo_h = sym_addr_h(gWo_h);
    __half* sXo_hi = sym_addr_h(gXo_hi); __half* sXo_lo = sym_addr_h(gXo_lo);

    cudaFuncSetAttribute(gemm_mma, cudaFuncAttributeMaxDynamicSharedMemorySize, GEMM_SMEM);
    cudaFuncSetAttribute(attn_mma, cudaFuncAttributeMaxDynamicSharedMemorySize, ATTN_SMEM);

    // 1. present caches
    cudaMemcpyAsync(out_k, kcache, (size_t)CACHE_SZ * sizeof(float), cudaMemcpyDeviceToDevice, 0);
    cudaMemcpyAsync(out_v, vcache, (size_t)CACHE_SZ * sizeof(float), cudaMemcpyDeviceToDevice, 0);

    // 2. conversions
    conv_hilo<<<(BB*QN*HID + 255) / 256, 256>>>(hidden, sA_hi, sA_lo, BB*QN*HID);
    conv_T_h<<<dim3(NQKV / 32, HID / 32), dim3(32, 8)>>>(w_qkv, sWq_h, HID, NQKV);
    conv_T_h<<<dim3(HID / 32, (HKV*DD) / 32), dim3(32, 8)>>>(w_o, sWo_h, HKV*DD, HID);
    kv_h_past<<<(BB*HKV*PAST*DD + 255) / 256, 256>>>(kcache, vcache);

    // 3. QKV projection (2-term fp16)
    gemm_mma<<<dim3(NQKV / 128, (BB*QN) / 128), 128, GEMM_SMEM>>>(
        sA_hi, sA_lo, sWq_h, s_qkv, BB*QN, NQKV, HID);

    // 4. RMSNorm + RoPE + scatter + fused fp16 emission
    qkv_post_kernel<<<dim3(48, QN, BB), 128>>>(rope, start, qw, kw, out_k, out_v);

    // 5. flash attention (LPT, log2 softmax, K/V double-buffered)
    attn_mma<<<dim3(QN / 64, HH, BB), 128, ATTN_SMEM>>>();

    // 6. group-sum + fp16 hi/lo
    group_sum_kernel<<<(BB*QN*HKV*DD + 255) / 256, 256>>>();

    // 7. output projection (2-term fp16)
    gemm_mma<<<dim3(HID / 128, (BB*QN) / 128), 128, GEMM_SMEM>>>(
        sXo_hi, sXo_lo, sWo_h, out_attn, BB*QN, HID, HKV*DD);
}

// round 12
// speedup vs baseline: 1.5201x; 1.0467x over previous
#include <cuda_runtime.h>
#include <cuda_fp16.h>
#include <cstdint>

// ---------------- problem constants ----------------
#define BB    2
#define QN    1024
#define PAST  1024
#define MAXC  4096
#define HH    32
#define HKV   8
#define DD    128
#define HID   4096
#define KLEN  (PAST + QN)          // 2048
#define NQKV  ((HH + 2*HKV) * DD)  // 6144
#define GROUPS (HH / HKV)
#define SCALE 0.08838834764831845f
#define LOG2E 1.4426950408889634f

#define OUT_SZ1 (BB*QN*HID)
#define CACHE_SZ (BB*HKV*MAXC*DD)

// ---------------- scratch (device globals) ----------------
__device__ __align__(16) float g_qkv  [BB*QN*NQKV];
__device__ __align__(16) float g_attnO[BB*HH*QN*DD];

__device__ __align__(16) __half gA_hi [BB*QN*HID];
__device__ __align__(16) __half gA_lo [BB*QN*HID];
__device__ __align__(16) __half gWq_h [NQKV*HID];
__device__ __align__(16) __half gWo_h [HID*HKV*DD];
__device__ __align__(16) __half gXo_hi[BB*QN*HKV*DD];
__device__ __align__(16) __half gXo_lo[BB*QN*HKV*DD];

__device__ __align__(16) __half gQ_hi [BB*HH*QN*DD];
__device__ __align__(16) __half gQ_lo [BB*HH*QN*DD];
__device__ __align__(16) __half gKc_h [BB*HKV*KLEN*DD];
__device__ __align__(16) __half gVc_h [BB*HKV*KLEN*DD];

// ================= PTX helpers =================
__device__ __forceinline__ uint32_t smem_u32(const void* p) {
    uint32_t a;
    asm("{ .reg .u64 t; cvta.to.shared.u64 t, %1; cvt.u32.u64 %0, t; }" : "=r"(a) : "l"(p));
    return a;
}
__device__ __forceinline__ void ldm_x4(uint32_t* r, uint32_t addr) {
    asm volatile("ldmatrix.sync.aligned.m8n8.x4.shared.b16 {%0,%1,%2,%3}, [%4];"
                 : "=r"(r[0]), "=r"(r[1]), "=r"(r[2]), "=r"(r[3]) : "r"(addr));
}
__device__ __forceinline__ void ldm_x4t(uint32_t* r, uint32_t addr) {
    asm volatile("ldmatrix.sync.aligned.m8n8.x4.trans.shared.b16 {%0,%1,%2,%3}, [%4];"
                 : "=r"(r[0]), "=r"(r[1]), "=r"(r[2]), "=r"(r[3]) : "r"(addr));
}
__device__ __forceinline__ void mma_f16(float* d, const uint32_t* a, const uint32_t* b) {
    asm volatile(
        "mma.sync.aligned.m16n8k16.row.col.f32.f16.f16.f32 "
        "{%0,%1,%2,%3}, {%4,%5,%6,%7}, {%8,%9}, {%0,%1,%2,%3};"
        : "+f"(d[0]), "+f"(d[1]), "+f"(d[2]), "+f"(d[3])
        : "r"(a[0]), "r"(a[1]), "r"(a[2]), "r"(a[3]), "r"(b[0]), "r"(b[1]));
}
__device__ __forceinline__ void cp16(uint32_t dst, const void* src) {
    asm volatile("cp.async.cg.shared.global [%0], [%1], 16;" :: "r"(dst), "l"(src));
}
__device__ __forceinline__ uint32_t pack_h2(float x, float y) {
    __half2 h = __floats2half2_rn(x, y);
    return *(uint32_t*)&h;
}
__device__ __forceinline__ float ex2(float x) {
    float y;
    asm("ex2.approx.f32 %0, %1;" : "=f"(y) : "f"(x));
    return y;
}

// ================= conversion kernels =================
__global__ void conv_hilo(const float* __restrict__ src,
                          __half* __restrict__ hi, __half* __restrict__ lo, int n) {
    int i = blockIdx.x * 256 + threadIdx.x;
    if (i >= n) return;
    float x = src[i];
    __half h = __float2half_rn(x);
    hi[i] = h;
    lo[i] = __float2half_rn(x - __half2float(h));
}

// src [K][N] fp32 -> hi-only [N][K] fp16 (transposed)
__global__ void conv_T_h(const float* __restrict__ src, __half* __restrict__ hi,
                         int K, int N) {
    __shared__ float t[32][33];
    int bn = blockIdx.x * 32, bk = blockIdx.y * 32;
    int x = threadIdx.x, y = threadIdx.y;
    #pragma unroll
    for (int i = 0; i < 32; i += 8)
        t[y + i][x] = src[(long)(bk + y + i) * N + bn + x];
    __syncthreads();
    #pragma unroll
    for (int i = 0; i < 32; i += 8)
        hi[(long)(bn + y + i) * K + bk + x] = __float2half_rn(t[x][y + i]);
}

// fused: copy full caches to output present-caches + PAST rows -> fp16
__global__ void cache_copy_conv(const float* __restrict__ kc, const float* __restrict__ vc,
                                float* __restrict__ out_k, float* __restrict__ out_v) {
    long i = (long)blockIdx.x * 256 + threadIdx.x;
    if (i >= (long)CACHE_SZ) return;
    float kx = kc[i], vx = vc[i];
    out_k[i] = kx;
    out_v[i] = vx;
    int d = (int)(i & (DD - 1));
    long t = i >> 7;
    int pos = (int)(t & (MAXC - 1));
    if (pos < PAST) {
        t >>= 12;                           // t = b*HKV + h
        long dst = (t * KLEN + pos) * DD + d;
        gKc_h[dst] = __float2half_rn(kx);
        gVc_h[dst] = __float2half_rn(vx);
    }
}

// ================= warp-MMA fp16 2-term GEMM (4-stage, 2 chunks per barrier) =================
#define TILE_B  8192
#define STAGE_B (3 * TILE_B)              // Ah, Al, Bh = 24576
#define NST     4
#define GEMM_SMEM (NST * STAGE_B)         // 98304

__device__ __forceinline__ uint32_t swz(int row, int ch) {
    return (uint32_t)(row * 64 + ((ch ^ ((row >> 1) & 3)) << 4));
}

__device__ __forceinline__ void fill_stage(
    uint32_t sb, int kt, int m0, int n0, int K,
    const __half* Ahi, const __half* Alo, const __half* Bh, int tid)
{
    long k0 = (long)kt * 32;
    const __half* bases[3] = {Ahi, Alo, Bh};
    #pragma unroll
    for (int t = 0; t < 3; t++) {
        const __half* bp = bases[t];
        int r0 = (t < 2) ? m0 : n0;
        #pragma unroll
        for (int i = 0; i < 4; i++) {
            int idx = tid + i * 128;
            int row = idx >> 2, ch = idx & 3;
            cp16(sb + t * TILE_B + swz(row, ch), bp + (long)(r0 + row) * K + k0 + ch * 8);
        }
    }
}

__global__ void __launch_bounds__(128, 2) gemm_mma(
    const __half* __restrict__ Ahi, const __half* __restrict__ Alo,
    const __half* __restrict__ Bh,
    float* __restrict__ C, int M, int N, int K)
{
    extern __shared__ char smraw[];
    uint32_t s0 = smem_u32(smraw);
    int tid = threadIdx.x, lane = tid & 31, wid = tid >> 5;
    int wm = wid & 1, wn = wid >> 1;
    int m0 = blockIdx.y * 128, n0 = blockIdx.x * 128;

    float acc[4][8][4];
    #pragma unroll
    for (int i = 0; i < 4; i++)
        #pragma unroll
        for (int j = 0; j < 8; j++)
            #pragma unroll
            for (int k = 0; k < 4; k++) acc[i][j][k] = 0.f;

    int nk = K >> 5;                   // always even (32 or 128)
    #pragma unroll
    for (int p = 0; p < 4; p++) {
        fill_stage(s0 + p * STAGE_B, p, m0, n0, K, Ahi, Alo, Bh, tid);
        asm volatile("cp.async.commit_group;" ::: "memory");
    }

    int a_row = wm * 64 + (lane & 15);
    int a_cb  = lane >> 4;
    int b_row = wn * 64 + (lane & 7) + (lane >> 4) * 8;
    int b_cb  = (lane >> 3) & 1;

    for (int kt = 0; kt < nk; kt += 2) {
        asm volatile("cp.async.wait_group 2;" ::: "memory");
        __syncthreads();   // stages kt,kt+1 ready; prev iter's compute done -> refills safe

        if (kt + 2 < nk) {
            fill_stage(s0 + ((kt + 2) & 3) * STAGE_B, kt + 2, m0, n0, K, Ahi, Alo, Bh, tid);
            asm volatile("cp.async.commit_group;" ::: "memory");
        }
        if (kt + 3 < nk) {
            fill_stage(s0 + ((kt + 3) & 3) * STAGE_B, kt + 3, m0, n0, K, Ahi, Alo, Bh, tid);
            asm volatile("cp.async.commit_group;" ::: "memory");
        }

        #pragma unroll
        for (int half = 0; half < 2; half++) {
            uint32_t sb = s0 + ((kt + half) & 3) * STAGE_B;
            uint32_t sbB = sb + 2 * TILE_B;

            uint32_t a[2][4][4];
            uint32_t bfr[2][4];
            #pragma unroll
            for (int hl = 0; hl < 2; hl++)
                #pragma unroll
                for (int mt = 0; mt < 4; mt++)
                    ldm_x4(a[hl][mt], sb + hl * TILE_B + swz(a_row + mt * 16, a_cb));
            ldm_x4(bfr[0], sbB + swz(b_row, b_cb));

            #pragma unroll
            for (int idx = 0; idx < 8; idx++) {
                int buf = idx & 1;
                if (idx < 7) {
                    int nks = (idx + 1) >> 2, nnp = (idx + 1) & 3;
                    ldm_x4(bfr[buf ^ 1], sbB + swz(b_row + nnp * 16, nks * 2 + b_cb));
                }
                int np = idx & 3;
                uint32_t* bh = bfr[buf];
                #pragma unroll
                for (int mt = 0; mt < 4; mt++)
                    #pragma unroll
                    for (int nt = 0; nt < 2; nt++) {
                        float* d = acc[mt][np * 2 + nt];
                        mma_f16(d, a[0][mt], &bh[nt * 2]);
                        mma_f16(d, a[1][mt], &bh[nt * 2]);
                    }
                if (idx == 3) {
                    #pragma unroll
                    for (int hl = 0; hl < 2; hl++)
                        #pragma unroll
                        for (int mt = 0; mt < 4; mt++)
                            ldm_x4(a[hl][mt], sb + hl * TILE_B + swz(a_row + mt * 16, 2 + a_cb));
                }
            }
        }
    }

    int row0 = m0 + wm * 64 + (lane >> 2);
    int col0 = n0 + wn * 64 + (lane & 3) * 2;
    #pragma unroll
    for (int mt = 0; mt < 4; mt++)
        #pragma unroll
        for (int nt = 0; nt < 8; nt++) {
            float* d = acc[mt][nt];
            long r = row0 + mt * 16;
            long c = col0 + nt * 8;
            *(float2*)(C + r * N + c)       = make_float2(d[0], d[1]);
            *(float2*)(C + (r + 8) * N + c) = make_float2(d[2], d[3]);
        }
}

// ---------------- RMSNorm + RoPE + scatter + fused fp16 emission ----------------
__global__ void qkv_post_kernel(const float* __restrict__ rope,
                                const int*   __restrict__ start,
                                const float* __restrict__ qw,
                                const float* __restrict__ kw,
                                float* __restrict__ out_k,
                                float* __restrict__ out_v)
{
    int slot = blockIdx.x;
    int q    = blockIdx.y;
    int b    = blockIdx.z;
    int tid  = threadIdx.x;
    long row = ((long)b * QN + q) * NQKV;
    float x = g_qkv[row + (long)slot * DD + tid];
    int pos = start[b] + q;

    if (slot >= 40) {  // V
        int h = slot - 40;
        out_v[(((long)b * HKV + h) * MAXC + pos) * DD + tid] = x;
        gVc_h[(((long)b * HKV + h) * KLEN + pos) * DD + tid] = __float2half_rn(x);
        return;
    }

    __shared__ float red[4];
    __shared__ float sm[DD];
    float v2 = x * x;
    #pragma unroll
    for (int m = 16; m; m >>= 1) v2 += __shfl_xor_sync(0xffffffffu, v2, m);
    if ((tid & 31) == 0) red[tid >> 5] = v2;
    __syncthreads();
    float tot = red[0] + red[1] + red[2] + red[3];
    float scl = rsqrtf(tot * (1.f / DD) + 1e-6f);
    const float* w = (slot < 32) ? qw : kw;
    sm[tid] = x * scl * w[tid];
    __syncthreads();

    int i = (tid < 64) ? tid : tid - 64;
    float c = rope[(long)pos * DD + i];
    float s = rope[(long)pos * DD + 64 + i];
    float x1 = sm[i], x2 = sm[i + 64];
    float o = (tid < 64) ? (x1 * c - x2 * s) : (x2 * c + x1 * s);

    if (slot < 32) {   // Q: scaled fp16 hi/lo (log2 domain)
        float xs = o * (SCALE * LOG2E);
        long qi = (((long)b * HH + slot) * QN + q) * DD + tid;
        __half qh = __float2half_rn(xs);
        gQ_hi[qi] = qh;
        gQ_lo[qi] = __float2half_rn(xs - __half2float(qh));
    } else {           // K
        int h = slot - 32;
        out_k[(((long)b * HKV + h) * MAXC + pos) * DD + tid] = o;
        gKc_h[(((long)b * HKV + h) * KLEN + pos) * DD + tid] = __float2half_rn(o);
    }
}

// ================= flash attention (fp16, Q hi/lo + P hi/lo; K/V double-buffered) =================
#define APITCHB 272
#define AQ 64
#define ATILE (AQ * APITCHB)               // 17408
#define ATTN_SMEM (6 * ATILE)              // 104448

__device__ __forceinline__ void load_tile_h(uint32_t dst,
    const __half* src, long rowbase, int tid)
{
    #pragma unroll
    for (int i = 0; i < 8; i++) {
        int idx = tid + i * 128;
        int row = idx >> 4, ch = idx & 15;
        cp16(dst + row * APITCHB + ch * 16, src + rowbase + (long)row * DD + (ch << 3));
    }
}

__global__ void __launch_bounds__(128, 2) attn_mma()
{
    extern __shared__ char smraw[];
    uint32_t sQh = smem_u32(smraw);
    uint32_t sQl = sQh + ATILE;
    uint32_t sK0 = sQh + 2 * ATILE;
    uint32_t sV0 = sQh + 4 * ATILE;
    int tid = threadIdx.x, lane = tid & 31, w = tid >> 5;
    int qt = gridDim.x - 1 - blockIdx.x;   // LPT
    int h = blockIdx.y, b = blockIdx.z;
    int kvh = h >> 2;
    int q0 = qt * 64;

    long qbase  = ((long)(b * HH + h) * QN + q0) * DD;
    long kvbase = (long)(b * HKV + kvh) * KLEN * DD;

    load_tile_h(sQh, gQ_hi, qbase, tid);
    load_tile_h(sQl, gQ_lo, qbase, tid);
    load_tile_h(sK0, gKc_h, kvbase, tid);
    load_tile_h(sV0, gVc_h, kvbase, tid);
    asm volatile("cp.async.commit_group;" ::: "memory");
    load_tile_h(sK0 + ATILE, gKc_h, kvbase + 64 * DD, tid);
    load_tile_h(sV0 + ATILE, gVc_h, kvbase + 64 * DD, tid);
    asm volatile("cp.async.commit_group;" ::: "memory");

    const int nc = 17 + qt;

    float O[16][4];
    #pragma unroll
    for (int i = 0; i < 16; i++)
        #pragma unroll
        for (int j = 0; j < 4; j++) O[i][j] = 0.f;
    float m0 = -1e30f, m1 = -1e30f, l0 = 0.f, l1 = 0.f;

    const int a_row  = w * 16 + (lane & 15);
    const int a_kb   = (lane >> 4) * 16;
    const int b_row  = (lane & 7) + (lane >> 4) * 8;
    const int b_kb   = ((lane >> 3) & 1) * 16;
    const int v_row  = lane & 15;
    const int v_col  = (lane >> 4) * 8;

    for (int c = 0; c < nc; c++) {
        int buf = c & 1;
        uint32_t sK = sK0 + buf * ATILE;
        uint32_t sV = sV0 + buf * ATILE;

        asm volatile("cp.async.wait_group 1;" ::: "memory");
        __syncthreads();

        // ---- S = Q K^T (2-term) ----
        float S[8][4];
        #pragma unroll
        for (int j = 0; j < 8; j++)
            #pragma unroll
            for (int k = 0; k < 4; k++) S[j][k] = 0.f;

        #pragma unroll
        for (int ks = 0; ks < 8; ks++) {
            uint32_t qh[4], ql[4];
            uint32_t qa = sQh + a_row * APITCHB + ks * 32 + a_kb;
            ldm_x4(qh, qa);
            ldm_x4(ql, qa + ATILE);
            #pragma unroll
            for (int np = 0; np < 4; np++) {
                uint32_t kf[4];
                ldm_x4(kf, sK + (np * 16 + b_row) * APITCHB + ks * 32 + b_kb);
                #pragma unroll
                for (int nt = 0; nt < 2; nt++) {
                    float* d = S[np * 2 + nt];
                    mma_f16(d, qh, &kf[nt * 2]);
                    mma_f16(d, ql, &kf[nt * 2]);
                }
            }
        }

        if (c == nc - 1) {
            int klim0 = PAST + q0 + w * 16 + (lane >> 2);
            int klim1 = klim0 + 8;
            int kb = c * 64;
            #pragma unroll
            for (int j = 0; j < 8; j++) {
                int col = kb + j * 8 + (lane & 3) * 2;
                if (col > klim0)     S[j][0] = -1e30f;
                if (col + 1 > klim0) S[j][1] = -1e30f;
                if (col > klim1)     S[j][2] = -1e30f;
                if (col + 1 > klim1) S[j][3] = -1e30f;
            }
        }

        // ---- online softmax (base-2) ----
        float mx0 = -1e30f, mx1 = -1e30f;
        #pragma unroll
        for (int j = 0; j < 8; j++) {
            mx0 = fmaxf(mx0, fmaxf(S[j][0], S[j][1]));
            mx1 = fmaxf(mx1, fmaxf(S[j][2], S[j][3]));
        }
        mx0 = fmaxf(mx0, __shfl_xor_sync(0xffffffffu, mx0, 1));
        mx0 = fmaxf(mx0, __shfl_xor_sync(0xffffffffu, mx0, 2));
        mx1 = fmaxf(mx1, __shfl_xor_sync(0xffffffffu, mx1, 1));
        mx1 = fmaxf(mx1, __shfl_xor_sync(0xffffffffu, mx1, 2));
        float mn0 = fmaxf(m0, mx0), mn1 = fmaxf(m1, mx1);
        float al0 = ex2(m0 - mn0), al1 = ex2(m1 - mn1);
        float r0 = 0.f, r1 = 0.f;
        #pragma unroll
        for (int j = 0; j < 8; j++) {
            S[j][0] = ex2(S[j][0] - mn0);
            S[j][1] = ex2(S[j][1] - mn0);
            S[j][2] = ex2(S[j][2] - mn1);
            S[j][3] = ex2(S[j][3] - mn1);
            r0 += S[j][0] + S[j][1];
            r1 += S[j][2] + S[j][3];
        }
        r0 += __shfl_xor_sync(0xffffffffu, r0, 1);
        r0 += __shfl_xor_sync(0xffffffffu, r0, 2);
        r1 += __shfl_xor_sync(0xffffffffu, r1, 1);
        r1 += __shfl_xor_sync(0xffffffffu, r1, 2);
        l0 = l0 * al0 + r0;
        l1 = l1 * al1 + r1;
        m0 = mn0; m1 = mn1;
        #pragma unroll
        for (int i = 0; i < 16; i++) {
            O[i][0] *= al0; O[i][1] *= al0;
            O[i][2] *= al1; O[i][3] *= al1;
        }

        // ---- P -> fp16 hi/lo A-frags ----
        uint32_t pa_h[4][4], pa_l[4][4];
        #pragma unroll
        for (int kt = 0; kt < 4; kt++) {
            int j0 = 2 * kt, j1 = 2 * kt + 1;
            float v00 = S[j0][0], v01 = S[j0][1], v02 = S[j0][2], v03 = S[j0][3];
            float v10 = S[j1][0], v11 = S[j1][1], v12 = S[j1][2], v13 = S[j1][3];
            pa_h[kt][0] = pack_h2(v00, v01);
            pa_h[kt][1] = pack_h2(v02, v03);
            pa_h[kt][2] = pack_h2(v10, v11);
            pa_h[kt][3] = pack_h2(v12, v13);
            __half2* hp;
            hp = (__half2*)&pa_h[kt][0];
            pa_l[kt][0] = pack_h2(v00 - __half2float(hp->x), v01 - __half2float(hp->y));
            hp = (__half2*)&pa_h[kt][1];
            pa_l[kt][1] = pack_h2(v02 - __half2float(hp->x), v03 - __half2float(hp->y));
            hp = (__half2*)&pa_h[kt][2];
            pa_l[kt][2] = pack_h2(v10 - __half2float(hp->x), v11 - __half2float(hp->y));
            hp = (__half2*)&pa_h[kt][3];
            pa_l[kt][3] = pack_h2(v12 - __half2float(hp->x), v13 - __half2float(hp->y));
        }

        // ---- O += P V (2-term) ----
        #pragma unroll
        for (int kt = 0; kt < 4; kt++) {
            #pragma unroll
            for (int np = 0; np < 8; np++) {
                uint32_t vf[4];
                ldm_x4t(vf, sV + (kt * 16 + v_row) * APITCHB + (np * 16 + v_col) * 2);
                #pragma unroll
                for (int nt = 0; nt < 2; nt++) {
                    float* d = O[np * 2 + nt];
                    mma_f16(d, pa_h[kt], &vf[nt * 2]);
                    mma_f16(d, pa_l[kt], &vf[nt * 2]);
                }
            }
        }
        __syncthreads();

        if (c + 2 < nc) {
            long nb = kvbase + (long)(c + 2) * 64 * DD;
            load_tile_h(sK, gKc_h, nb, tid);
            load_tile_h(sV, gVc_h, nb, tid);
        }
        asm volatile("cp.async.commit_group;" ::: "memory");
    }

    float inv0 = 1.f / l0, inv1 = 1.f / l1;
    int row0 = q0 + w * 16 + (lane >> 2);
    float* ob = g_attnO + ((long)(b * HH + h) * QN) * DD;
    #pragma unroll
    for (int np = 0; np < 16; np++) {
        int col = np * 8 + (lane & 3) * 2;
        *(float2*)(ob + (long)row0 * DD + col)       = make_float2(O[np][0] * inv0, O[np][1] * inv0);
        *(float2*)(ob + (long)(row0 + 8) * DD + col) = make_float2(O[np][2] * inv1, O[np][3] * inv1);
    }
}

// ---------------- group sum + fp16 hi/lo conversion ----------------
__global__ void group_sum_kernel()
{
    long i = (long)blockIdx.x * 256 + threadIdx.x;
    if (i >= (long)BB * QN * HKV * DD) return;
    int d = (int)(i & (DD - 1));
    long t = i >> 7;
    int kvh = (int)(t & (HKV - 1));
    t >>= 3;
    int q = (int)(t % QN);
    int b = (int)(t / QN);
    float sum = 0.f;
    #pragma unroll
    for (int g = 0; g < GROUPS; g++)
        sum += g_attnO[(((long)b * HH + kvh * GROUPS + g) * QN + q) * DD + d];
    __half h = __float2half_rn(sum);
    gXo_hi[i] = h;
    gXo_lo[i] = __float2half_rn(sum - __half2float(h));
}

// ---------------- launch ----------------
static __half* sym_addr_h(const void* sym) {
    void* p = nullptr;
    cudaGetSymbolAddress(&p, sym);
    return (__half*)p;
}
static float* sym_addr_f(const void* sym) {
    void* p = nullptr;
    cudaGetSymbolAddress(&p, sym);
    return (float*)p;
}

extern "C" void kernel_launch(void* const* d_in, const int* in_sizes, int n_in,
                              void* d_out, int out_size)
{
    const float* hidden = (const float*)d_in[0];
    const float* kcache = (const float*)d_in[1];
    const float* vcache = (const float*)d_in[2];
    const float* rope   = (const float*)d_in[3];
    const int*   start  = (const int*)  d_in[5];
    const float* w_qkv  = (const float*)d_in[6];
    const float* w_o    = (const float*)d_in[7];
    const float* qw     = (const float*)d_in[8];
    const float* kw     = (const float*)d_in[9];

    float* out      = (float*)d_out;
    float* out_attn = out;
    float* out_k    = out + OUT_SZ1;
    float* out_v    = out + OUT_SZ1 + CACHE_SZ;

    float* s_qkv = sym_addr_f(g_qkv);
    __half* sA_hi = sym_addr_h(gA_hi);  __half* sA_lo = sym_addr_h(gA_lo);
    __half* sWq_h = sym_addr_h(gWq_h);  __half* sWo_h = sym_addr_h(gWo_h);
    __half* sXo_hi = sym_addr_h(gXo_hi); __half* sXo_lo = sym_addr_h(gXo_lo);

    cudaFuncSetAttribute(gemm_mma, cudaFuncAttributeMaxDynamicSharedMemorySize, GEMM_SMEM);
    cudaFuncSetAttribute(attn_mma, cudaFuncAttributeMaxDynamicSharedMemorySize, ATTN_SMEM);

    // 1. fused cache copy + PAST fp16 conversion
    cache_copy_conv<<<(CACHE_SZ + 255) / 256, 256>>>(kcache, vcache, out_k, out_v);

    // 2. conversions
    conv_hilo<<<(BB*QN*HID + 255) / 256, 256>>>(hidden, sA_hi, sA_lo, BB*QN*HID);
    conv_T_h<<<dim3(NQKV / 32, HID / 32), dim3(32, 8)>>>(w_qkv, sWq_h, HID, NQKV);
    conv_T_h<<<dim3(HID / 32, (HKV*DD) / 32), dim3(32, 8)>>>(w_o, sWo_h, HKV*DD, HID);

    // 3. QKV projection (2-term fp16, 2-chunk barriers)
    gemm_mma<<<dim3(NQKV / 128, (BB*QN) / 128), 128, GEMM_SMEM>>>(
        sA_hi, sA_lo, sWq_h, s_qkv, BB*QN, NQKV, HID);

    // 4. RMSNorm + RoPE + scatter + fused fp16 emission
    qkv_post_kernel<<<dim3(48, QN, BB), 128>>>(rope, start, qw, kw, out_k, out_v);

    // 5. flash attention
    attn_mma<<<dim3(QN / 64, HH, BB), 128, ATTN_SMEM>>>();

    // 6. group-sum + fp16 hi/lo
    group_sum_kernel<<<(BB*QN*HKV*DD + 255) / 256, 256>>>();

    // 7. output projection
    gemm_mma<<<dim3(HID / 128, (BB*QN) / 128), 128, GEMM_SMEM>>>(
        sXo_hi, sXo_lo, sWo_h, out_attn, BB*QN, HID, HKV*DD);
}

// round 13
// speedup vs baseline: 1.5361x; 1.0105x over previous
#include <cuda_runtime.h>
#include <cuda_fp16.h>
#include <cstdint>

// ---------------- problem constants ----------------
#define BB    2
#define QN    1024
#define PAST  1024
#define MAXC  4096
#define HH    32
#define HKV   8
#define DD    128
#define HID   4096
#define KLEN  (PAST + QN)          // 2048
#define NQKV  ((HH + 2*HKV) * DD)  // 6144
#define GROUPS (HH / HKV)
#define SCALE 0.08838834764831845f
#define LOG2E 1.4426950408889634f

#define OUT_SZ1 (BB*QN*HID)
#define CACHE_SZ (BB*HKV*MAXC*DD)   // == BB*QN*HID == 8388608

// ---------------- scratch (device globals) ----------------
__device__ __align__(16) float g_qkv  [BB*QN*NQKV];
__device__ __align__(16) float g_attnO[BB*HH*QN*DD];

__device__ __align__(16) __half gA_hi [BB*QN*HID];
__device__ __align__(16) __half gA_lo [BB*QN*HID];
__device__ __align__(16) __half gWq_h [NQKV*HID];
__device__ __align__(16) __half gWo_h [HID*HKV*DD];
__device__ __align__(16) __half gXo_hi[BB*QN*HKV*DD];
__device__ __align__(16) __half gXo_lo[BB*QN*HKV*DD];

__device__ __align__(16) __half gQ_hi [BB*HH*QN*DD];
__device__ __align__(16) __half gQ_lo [BB*HH*QN*DD];
__device__ __align__(16) __half gKc_h [BB*HKV*KLEN*DD];
__device__ __align__(16) __half gVc_h [BB*HKV*KLEN*DD];

// ================= PTX helpers =================
__device__ __forceinline__ uint32_t smem_u32(const void* p) {
    uint32_t a;
    asm("{ .reg .u64 t; cvta.to.shared.u64 t, %1; cvt.u32.u64 %0, t; }" : "=r"(a) : "l"(p));
    return a;
}
__device__ __forceinline__ void ldm_x4(uint32_t* r, uint32_t addr) {
    asm volatile("ldmatrix.sync.aligned.m8n8.x4.shared.b16 {%0,%1,%2,%3}, [%4];"
                 : "=r"(r[0]), "=r"(r[1]), "=r"(r[2]), "=r"(r[3]) : "r"(addr));
}
__device__ __forceinline__ void ldm_x4t(uint32_t* r, uint32_t addr) {
    asm volatile("ldmatrix.sync.aligned.m8n8.x4.trans.shared.b16 {%0,%1,%2,%3}, [%4];"
                 : "=r"(r[0]), "=r"(r[1]), "=r"(r[2]), "=r"(r[3]) : "r"(addr));
}
__device__ __forceinline__ void mma_f16(float* d, const uint32_t* a, const uint32_t* b) {
    asm volatile(
        "mma.sync.aligned.m16n8k16.row.col.f32.f16.f16.f32 "
        "{%0,%1,%2,%3}, {%4,%5,%6,%7}, {%8,%9}, {%0,%1,%2,%3};"
        : "+f"(d[0]), "+f"(d[1]), "+f"(d[2]), "+f"(d[3])
        : "r"(a[0]), "r"(a[1]), "r"(a[2]), "r"(a[3]), "r"(b[0]), "r"(b[1]));
}
__device__ __forceinline__ void cp16(uint32_t dst, const void* src) {
    asm volatile("cp.async.cg.shared.global [%0], [%1], 16;" :: "r"(dst), "l"(src));
}
__device__ __forceinline__ uint32_t pack_h2(float x, float y) {
    __half2 h = __floats2half2_rn(x, y);
    return *(uint32_t*)&h;
}
__device__ __forceinline__ float ex2(float x) {
    float y;
    asm("ex2.approx.f32 %0, %1;" : "=f"(y) : "f"(x));
    return y;
}

// ================= fused input prep =================
// caches: copy to present + PAST rows -> fp16 ; hidden -> fp16 hi/lo (same element count)
__global__ void prep_inputs(const float* __restrict__ hidden,
                            const float* __restrict__ kc, const float* __restrict__ vc,
                            float* __restrict__ out_k, float* __restrict__ out_v) {
    long i = (long)blockIdx.x * 256 + threadIdx.x;
    if (i >= (long)CACHE_SZ) return;
    float kx = kc[i], vx = vc[i];
    out_k[i] = kx;
    out_v[i] = vx;
    int d = (int)(i & (DD - 1));
    long t = i >> 7;
    int pos = (int)(t & (MAXC - 1));
    if (pos < PAST) {
        long tt = t >> 12;                  // b*HKV + h
        long dst = (tt * KLEN + pos) * DD + d;
        gKc_h[dst] = __float2half_rn(kx);
        gVc_h[dst] = __float2half_rn(vx);
    }
    float x = hidden[i];
    __half h = __float2half_rn(x);
    gA_hi[i] = h;
    gA_lo[i] = __float2half_rn(x - __half2float(h));
}

// src [K][N] fp32 -> hi-only [N][K] fp16 (transposed)
__global__ void conv_T_h(const float* __restrict__ src, __half* __restrict__ hi,
                         int K, int N) {
    __shared__ float t[32][33];
    int bn = blockIdx.x * 32, bk = blockIdx.y * 32;
    int x = threadIdx.x, y = threadIdx.y;
    #pragma unroll
    for (int i = 0; i < 32; i += 8)
        t[y + i][x] = src[(long)(bk + y + i) * N + bn + x];
    __syncthreads();
    #pragma unroll
    for (int i = 0; i < 32; i += 8)
        hi[(long)(bn + y + i) * K + bk + x] = __float2half_rn(t[x][y + i]);
}

// ================= warp-MMA fp16 2-term GEMM (4-stage, 2 chunks per barrier) =================
#define TILE_B  8192
#define STAGE_B (3 * TILE_B)              // Ah, Al, Bh = 24576
#define NST     4
#define GEMM_SMEM (NST * STAGE_B)         // 98304

__device__ __forceinline__ uint32_t swz(int row, int ch) {
    return (uint32_t)(row * 64 + ((ch ^ ((row >> 1) & 3)) << 4));
}

__device__ __forceinline__ void fill_stage(
    uint32_t sb, int kt, int m0, int n0, int K,
    const __half* Ahi, const __half* Alo, const __half* Bh, int tid)
{
    long k0 = (long)kt * 32;
    const __half* bases[3] = {Ahi, Alo, Bh};
    #pragma unroll
    for (int t = 0; t < 3; t++) {
        const __half* bp = bases[t];
        int r0 = (t < 2) ? m0 : n0;
        #pragma unroll
        for (int i = 0; i < 4; i++) {
            int idx = tid + i * 128;
            int row = idx >> 2, ch = idx & 3;
            cp16(sb + t * TILE_B + swz(row, ch), bp + (long)(r0 + row) * K + k0 + ch * 8);
        }
    }
}

__global__ void __launch_bounds__(128, 2) gemm_mma(
    const __half* __restrict__ Ahi, const __half* __restrict__ Alo,
    const __half* __restrict__ Bh,
    float* __restrict__ C, int M, int N, int K)
{
    extern __shared__ char smraw[];
    uint32_t s0 = smem_u32(smraw);
    int tid = threadIdx.x, lane = tid & 31, wid = tid >> 5;
    int wm = wid & 1, wn = wid >> 1;
    int m0 = blockIdx.y * 128, n0 = blockIdx.x * 128;

    float acc[4][8][4];
    #pragma unroll
    for (int i = 0; i < 4; i++)
        #pragma unroll
        for (int j = 0; j < 8; j++)
            #pragma unroll
            for (int k = 0; k < 4; k++) acc[i][j][k] = 0.f;

    int nk = K >> 5;
    #pragma unroll
    for (int p = 0; p < 4; p++) {
        fill_stage(s0 + p * STAGE_B, p, m0, n0, K, Ahi, Alo, Bh, tid);
        asm volatile("cp.async.commit_group;" ::: "memory");
    }

    int a_row = wm * 64 + (lane & 15);
    int a_cb  = lane >> 4;
    int b_row = wn * 64 + (lane & 7) + (lane >> 4) * 8;
    int b_cb  = (lane >> 3) & 1;

    for (int kt = 0; kt < nk; kt += 2) {
        asm volatile("cp.async.wait_group 2;" ::: "memory");
        __syncthreads();

        if (kt + 2 < nk) {
            fill_stage(s0 + ((kt + 2) & 3) * STAGE_B, kt + 2, m0, n0, K, Ahi, Alo, Bh, tid);
            asm volatile("cp.async.commit_group;" ::: "memory");
        }
        if (kt + 3 < nk) {
            fill_stage(s0 + ((kt + 3) & 3) * STAGE_B, kt + 3, m0, n0, K, Ahi, Alo, Bh, tid);
            asm volatile("cp.async.commit_group;" ::: "memory");
        }

        #pragma unroll
        for (int half = 0; half < 2; half++) {
            uint32_t sb = s0 + ((kt + half) & 3) * STAGE_B;
            uint32_t sbB = sb + 2 * TILE_B;

            uint32_t a[2][4][4];
            uint32_t bfr[2][4];
            #pragma unroll
            for (int hl = 0; hl < 2; hl++)
                #pragma unroll
                for (int mt = 0; mt < 4; mt++)
                    ldm_x4(a[hl][mt], sb + hl * TILE_B + swz(a_row + mt * 16, a_cb));
            ldm_x4(bfr[0], sbB + swz(b_row, b_cb));

            #pragma unroll
            for (int idx = 0; idx < 8; idx++) {
                int buf = idx & 1;
                if (idx < 7) {
                    int nks = (idx + 1) >> 2, nnp = (idx + 1) & 3;
                    ldm_x4(bfr[buf ^ 1], sbB + swz(b_row + nnp * 16, nks * 2 + b_cb));
                }
                int np = idx & 3;
                uint32_t* bh = bfr[buf];
                #pragma unroll
                for (int mt = 0; mt < 4; mt++)
                    #pragma unroll
                    for (int nt = 0; nt < 2; nt++) {
                        float* d = acc[mt][np * 2 + nt];
                        mma_f16(d, a[0][mt], &bh[nt * 2]);
                        mma_f16(d, a[1][mt], &bh[nt * 2]);
                    }
                if (idx == 3) {
                    #pragma unroll
                    for (int hl = 0; hl < 2; hl++)
                        #pragma unroll
                        for (int mt = 0; mt < 4; mt++)
                            ldm_x4(a[hl][mt], sb + hl * TILE_B + swz(a_row + mt * 16, 2 + a_cb));
                }
            }
        }
    }

    int row0 = m0 + wm * 64 + (lane >> 2);
    int col0 = n0 + wn * 64 + (lane & 3) * 2;
    #pragma unroll
    for (int mt = 0; mt < 4; mt++)
        #pragma unroll
        for (int nt = 0; nt < 8; nt++) {
            float* d = acc[mt][nt];
            long r = row0 + mt * 16;
            long c = col0 + nt * 8;
            *(float2*)(C + r * N + c)       = make_float2(d[0], d[1]);
            *(float2*)(C + (r + 8) * N + c) = make_float2(d[2], d[3]);
        }
}

// ---------------- RMSNorm + RoPE + scatter + fused fp16 emission (512 thr, 4 slots) ----------------
__global__ void qkv_post_kernel(const float* __restrict__ rope,
                                const int*   __restrict__ start,
                                const float* __restrict__ qw,
                                const float* __restrict__ kw,
                                float* __restrict__ out_k,
                                float* __restrict__ out_v)
{
    int sub  = threadIdx.x >> 7;            // 0..3
    int tid  = threadIdx.x & 127;
    int slot = blockIdx.x * 4 + sub;        // 0..47
    int q    = blockIdx.y;
    int b    = blockIdx.z;
    long row = ((long)b * QN + q) * NQKV;
    float x = g_qkv[row + (long)slot * DD + tid];
    int pos = start[b] + q;

    if (slot >= 40) {  // V (whole block is V slots -> safe early return)
        int h = slot - 40;
        out_v[(((long)b * HKV + h) * MAXC + pos) * DD + tid] = x;
        gVc_h[(((long)b * HKV + h) * KLEN + pos) * DD + tid] = __float2half_rn(x);
        return;
    }

    __shared__ float red[4][4];
    __shared__ float sm[4][DD];
    float v2 = x * x;
    #pragma unroll
    for (int m = 16; m; m >>= 1) v2 += __shfl_xor_sync(0xffffffffu, v2, m);
    if ((tid & 31) == 0) red[sub][tid >> 5] = v2;
    __syncthreads();
    float tot = red[sub][0] + red[sub][1] + red[sub][2] + red[sub][3];
    float scl = rsqrtf(tot * (1.f / DD) + 1e-6f);
    const float* w = (slot < 32) ? qw : kw;
    sm[sub][tid] = x * scl * w[tid];
    __syncthreads();

    int i = (tid < 64) ? tid : tid - 64;
    float c = rope[(long)pos * DD + i];
    float s = rope[(long)pos * DD + 64 + i];
    float x1 = sm[sub][i], x2 = sm[sub][i + 64];
    float o = (tid < 64) ? (x1 * c - x2 * s) : (x2 * c + x1 * s);

    if (slot < 32) {   // Q: scaled fp16 hi/lo (log2 domain)
        float xs = o * (SCALE * LOG2E);
        long qi = (((long)b * HH + slot) * QN + q) * DD + tid;
        __half qh = __float2half_rn(xs);
        gQ_hi[qi] = qh;
        gQ_lo[qi] = __float2half_rn(xs - __half2float(qh));
    } else {           // K
        int h = slot - 32;
        out_k[(((long)b * HKV + h) * MAXC + pos) * DD + tid] = o;
        gKc_h[(((long)b * HKV + h) * KLEN + pos) * DD + tid] = __float2half_rn(o);
    }
}

// ================= flash attention (Q frags in regs, 3-stage K/V ring, 1 sync/chunk) =================
#define APITCHB 272
#define AQ 64
#define ATILE (AQ * APITCHB)               // 17408
#define ATTN_SMEM (6 * ATILE)              // 104448 (ring of 3 K/V stages; Q bootstraps in tiles 4,5)

__device__ __forceinline__ void load_tile_h(uint32_t dst,
    const __half* src, long rowbase, int tid)
{
    #pragma unroll
    for (int i = 0; i < 8; i++) {
        int idx = tid + i * 128;
        int row = idx >> 4, ch = idx & 15;
        cp16(dst + row * APITCHB + ch * 16, src + rowbase + (long)row * DD + (ch << 3));
    }
}

__global__ void __launch_bounds__(128, 2) attn_mma()
{
    extern __shared__ char smraw[];
    uint32_t T0 = smem_u32(smraw);   // tiles T0..T5; stage s: K=T(2s), V=T(2s+1)
    int tid = threadIdx.x, lane = tid & 31, w = tid >> 5;
    int qt = gridDim.x - 1 - blockIdx.x;   // LPT
    int h = blockIdx.y, b = blockIdx.z;
    int kvh = h >> 2;
    int q0 = qt * 64;

    long qbase  = ((long)(b * HH + h) * QN + q0) * DD;
    long kvbase = (long)(b * HKV + kvh) * KLEN * DD;

    const int a_row  = w * 16 + (lane & 15);
    const int a_kb   = (lane >> 4) * 16;
    const int b_row  = (lane & 7) + (lane >> 4) * 8;
    const int b_kb   = ((lane >> 3) & 1) * 16;
    const int v_row  = lane & 15;
    const int v_col  = (lane >> 4) * 8;

    // prologue: Q into tiles 4,5 + chunk0 (group0); chunk1 (group1)
    load_tile_h(T0 + 4 * ATILE, gQ_hi, qbase, tid);
    load_tile_h(T0 + 5 * ATILE, gQ_lo, qbase, tid);
    load_tile_h(T0,             gKc_h, kvbase, tid);
    load_tile_h(T0 + ATILE,     gVc_h, kvbase, tid);
    asm volatile("cp.async.commit_group;" ::: "memory");
    load_tile_h(T0 + 2 * ATILE, gKc_h, kvbase + 64 * DD, tid);
    load_tile_h(T0 + 3 * ATILE, gVc_h, kvbase + 64 * DD, tid);
    asm volatile("cp.async.commit_group;" ::: "memory");

    asm volatile("cp.async.wait_group 1;" ::: "memory");
    __syncthreads();

    // hoist Q fragments into registers (frees tiles 4,5 for the ring)
    uint32_t qfr[8][2][4];
    #pragma unroll
    for (int ks = 0; ks < 8; ks++) {
        uint32_t qa = T0 + 4 * ATILE + a_row * APITCHB + ks * 32 + a_kb;
        ldm_x4(qfr[ks][0], qa);
        ldm_x4(qfr[ks][1], qa + ATILE);
    }

    const int nc = 17 + qt;

    float O[16][4];
    #pragma unroll
    for (int i = 0; i < 16; i++)
        #pragma unroll
        for (int j = 0; j < 4; j++) O[i][j] = 0.f;
    float m0 = -1e30f, m1 = -1e30f, l0 = 0.f, l1 = 0.f;

    for (int c = 0; c < nc; c++) {
        int st = c % 3;
        uint32_t sK = T0 + 2 * st * ATILE;
        uint32_t sV = sK + ATILE;

        asm volatile("cp.async.wait_group 1;" ::: "memory");
        __syncthreads();   // chunk c visible; compute c-1 finished everywhere (ring-safe)

        if (c + 2 < nc) {
            int rs = (c + 2) % 3;
            long nb = kvbase + (long)(c + 2) * 64 * DD;
            load_tile_h(T0 + 2 * rs * ATILE,         gKc_h, nb, tid);
            load_tile_h(T0 + (2 * rs + 1) * ATILE,   gVc_h, nb, tid);
        }
        asm volatile("cp.async.commit_group;" ::: "memory");

        // ---- S = Q K^T (2-term, Q from regs) ----
        float S[8][4];
        #pragma unroll
        for (int j = 0; j < 8; j++)
            #pragma unroll
            for (int k = 0; k < 4; k++) S[j][k] = 0.f;

        #pragma unroll
        for (int ks = 0; ks < 8; ks++) {
            #pragma unroll
            for (int np = 0; np < 4; np++) {
                uint32_t kf[4];
                ldm_x4(kf, sK + (np * 16 + b_row) * APITCHB + ks * 32 + b_kb);
                #pragma unroll
                for (int nt = 0; nt < 2; nt++) {
                    float* d = S[np * 2 + nt];
                    mma_f16(d, qfr[ks][0], &kf[nt * 2]);
                    mma_f16(d, qfr[ks][1], &kf[nt * 2]);
                }
            }
        }

        if (c == nc - 1) {
            int klim0 = PAST + q0 + w * 16 + (lane >> 2);
            int klim1 = klim0 + 8;
            int kb = c * 64;
            #pragma unroll
            for (int j = 0; j < 8; j++) {
                int col = kb + j * 8 + (lane & 3) * 2;
                if (col > klim0)     S[j][0] = -1e30f;
                if (col + 1 > klim0) S[j][1] = -1e30f;
                if (col > klim1)     S[j][2] = -1e30f;
                if (col + 1 > klim1) S[j][3] = -1e30f;
            }
        }

        // ---- online softmax (base-2) ----
        float mx0 = -1e30f, mx1 = -1e30f;
        #pragma unroll
        for (int j = 0; j < 8; j++) {
            mx0 = fmaxf(mx0, fmaxf(S[j][0], S[j][1]));
            mx1 = fmaxf(mx1, fmaxf(S[j][2], S[j][3]));
        }
        mx0 = fmaxf(mx0, __shfl_xor_sync(0xffffffffu, mx0, 1));
        mx0 = fmaxf(mx0, __shfl_xor_sync(0xffffffffu, mx0, 2));
        mx1 = fmaxf(mx1, __shfl_xor_sync(0xffffffffu, mx1, 1));
        mx1 = fmaxf(mx1, __shfl_xor_sync(0xffffffffu, mx1, 2));
        float mn0 = fmaxf(m0, mx0), mn1 = fmaxf(m1, mx1);
        float al0 = ex2(m0 - mn0), al1 = ex2(m1 - mn1);
        float r0 = 0.f, r1 = 0.f;
        #pragma unroll
        for (int j = 0; j < 8; j++) {
            S[j][0] = ex2(S[j][0] - mn0);
            S[j][1] = ex2(S[j][1] - mn0);
            S[j][2] = ex2(S[j][2] - mn1);
            S[j][3] = ex2(S[j][3] - mn1);
            r0 += S[j][0] + S[j][1];
            r1 += S[j][2] + S[j][3];
        }
        r0 += __shfl_xor_sync(0xffffffffu, r0, 1);
        r0 += __shfl_xor_sync(0xffffffffu, r0, 2);
        r1 += __shfl_xor_sync(0xffffffffu, r1, 1);
        r1 += __shfl_xor_sync(0xffffffffu, r1, 2);
        l0 = l0 * al0 + r0;
        l1 = l1 * al1 + r1;
        m0 = mn0; m1 = mn1;
        #pragma unroll
        for (int i = 0; i < 16; i++) {
            O[i][0] *= al0; O[i][1] *= al0;
            O[i][2] *= al1; O[i][3] *= al1;
        }

        // ---- P -> fp16 hi/lo A-frags ----
        uint32_t pa_h[4][4], pa_l[4][4];
        #pragma unroll
        for (int kt = 0; kt < 4; kt++) {
            int j0 = 2 * kt, j1 = 2 * kt + 1;
            float v00 = S[j0][0], v01 = S[j0][1], v02 = S[j0][2], v03 = S[j0][3];
            float v10 = S[j1][0], v11 = S[j1][1], v12 = S[j1][2], v13 = S[j1][3];
            pa_h[kt][0] = pack_h2(v00, v01);
            pa_h[kt][1] = pack_h2(v02, v03);
            pa_h[kt][2] = pack_h2(v10, v11);
            pa_h[kt][3] = pack_h2(v12, v13);
            __half2* hp;
            hp = (__half2*)&pa_h[kt][0];
            pa_l[kt][0] = pack_h2(v00 - __half2float(hp->x), v01 - __half2float(hp->y));
            hp = (__half2*)&pa_h[kt][1];
            pa_l[kt][1] = pack_h2(v02 - __half2float(hp->x), v03 - __half2float(hp->y));
            hp = (__half2*)&pa_h[kt][2];
            pa_l[kt][2] = pack_h2(v10 - __half2float(hp->x), v11 - __half2float(hp->y));
            hp = (__half2*)&pa_h[kt][3];
            pa_l[kt][3] = pack_h2(v12 - __half2float(hp->x), v13 - __half2float(hp->y));
        }

        // ---- O += P V (2-term) ----
        #pragma unroll
        for (int kt = 0; kt < 4; kt++) {
            #pragma unroll
            for (int np = 0; np < 8; np++) {
                uint32_t vf[4];
                ldm_x4t(vf, sV + (kt * 16 + v_row) * APITCHB + (np * 16 + v_col) * 2);
                #pragma unroll
                for (int nt = 0; nt < 2; nt++) {
                    float* d = O[np * 2 + nt];
                    mma_f16(d, pa_h[kt], &vf[nt * 2]);
                    mma_f16(d, pa_l[kt], &vf[nt * 2]);
                }
            }
        }
    }

    float inv0 = 1.f / l0, inv1 = 1.f / l1;
    int row0 = q0 + w * 16 + (lane >> 2);
    float* ob = g_attnO + ((long)(b * HH + h) * QN) * DD;
    #pragma unroll
    for (int np = 0; np < 16; np++) {
        int col = np * 8 + (lane & 3) * 2;
        *(float2*)(ob + (long)row0 * DD + col)       = make_float2(O[np][0] * inv0, O[np][1] * inv0);
        *(float2*)(ob + (long)(row0 + 8) * DD + col) = make_float2(O[np][2] * inv1, O[np][3] * inv1);
    }
}

// ---------------- group sum + fp16 hi/lo conversion ----------------
__global__ void group_sum_kernel()
{
    long i = (long)blockIdx.x * 256 + threadIdx.x;
    if (i >= (long)BB * QN * HKV * DD) return;
    int d = (int)(i & (DD - 1));
    long t = i >> 7;
    int kvh = (int)(t & (HKV - 1));
    t >>= 3;
    int q = (int)(t % QN);
    int b = (int)(t / QN);
    float sum = 0.f;
    #pragma unroll
    for (int g = 0; g < GROUPS; g++)
        sum += g_attnO[(((long)b * HH + kvh * GROUPS + g) * QN + q) * DD + d];
    __half h = __float2half_rn(sum);
    gXo_hi[i] = h;
    gXo_lo[i] = __float2half_rn(sum - __half2float(h));
}

// ---------------- launch ----------------
static __half* sym_addr_h(const void* sym) {
    void* p = nullptr;
    cudaGetSymbolAddress(&p, sym);
    return (__half*)p;
}
static float* sym_addr_f(const void* sym) {
    void* p = nullptr;
    cudaGetSymbolAddress(&p, sym);
    return (float*)p;
}

extern "C" void kernel_launch(void* const* d_in, const int* in_sizes, int n_in,
                              void* d_out, int out_size)
{
    const float* hidden = (const float*)d_in[0];
    const float* kcache = (const float*)d_in[1];
    const float* vcache = (const float*)d_in[2];
    const float* rope   = (const float*)d_in[3];
    const int*   start  = (const int*)  d_in[5];
    const float* w_qkv  = (const float*)d_in[6];
    const float* w_o    = (const float*)d_in[7];
    const float* qw     = (const float*)d_in[8];
    const float* kw     = (const float*)d_in[9];

    float* out      = (float*)d_out;
    float* out_attn = out;
    float* out_k    = out + OUT_SZ1;
    float* out_v    = out + OUT_SZ1 + CACHE_SZ;

    float* s_qkv = sym_addr_f(g_qkv);
    __half* sA_hi = sym_addr_h(gA_hi);  __half* sA_lo = sym_addr_h(gA_lo);
    __half* sWq_h = sym_addr_h(gWq_h);  __half* sWo_h = sym_addr_h(gWo_h);
    __half* sXo_hi = sym_addr_h(gXo_hi); __half* sXo_lo = sym_addr_h(gXo_lo);

    cudaFuncSetAttribute(gemm_mma, cudaFuncAttributeMaxDynamicSharedMemorySize, GEMM_SMEM);
    cudaFuncSetAttribute(attn_mma, cudaFuncAttributeMaxDynamicSharedMemorySize, ATTN_SMEM);

    // 1. fused prep: cache copy + PAST fp16 + A hi/lo
    prep_inputs<<<(CACHE_SZ + 255) / 256, 256>>>(hidden, kcache, vcache, out_k, out_v);

    // 2. weight conversions
    conv_T_h<<<dim3(NQKV / 32, HID / 32), dim3(32, 8)>>>(w_qkv, sWq_h, HID, NQKV);
    conv_T_h<<<dim3(HID / 32, (HKV*DD) / 32), dim3(32, 8)>>>(w_o, sWo_h, HKV*DD, HID);

    // 3. QKV projection
    gemm_mma<<<dim3(NQKV / 128, (BB*QN) / 128), 128, GEMM_SMEM>>>(
        sA_hi, sA_lo, sWq_h, s_qkv, BB*QN, NQKV, HID);

    // 4. RMSNorm + RoPE + scatter + fp16 emission (4 slots/block)
    qkv_post_kernel<<<dim3(12, QN, BB), 512>>>(rope, start, qw, kw, out_k, out_v);

    // 5. flash attention (Q-in-regs, 3-stage ring)
    attn_mma<<<dim3(QN / 64, HH, BB), 128, ATTN_SMEM>>>();

    // 6. group-sum + fp16 hi/lo
    group_sum_kernel<<<(BB*QN*HKV*DD + 255) / 256, 256>>>();

    // 7. output projection
    gemm_mma<<<dim3(HID / 128, (BB*QN) / 128), 128, GEMM_SMEM>>>(
        sXo_hi, sXo_lo, sWo_h, out_attn, BB*QN, HID, HKV*DD);
}